// round 13
// baseline (speedup 1.0000x reference)
#include <cuda_runtime.h>
#include <cuda_bf16.h>
#include <cstdint>

// Problem dims
#define BB 2
#define LL 1024
#define DM 1024
#define DI 2048
#define NS 16
#define DTR 64
#define KC 4
#define MM (BB * LL)   // 2048 token rows
#define GG 8           // scan groups / split-K factor
#define GT (LL / GG)   // 128 t per group
#define NXP 128        // x_proj padded N (96 real + 32 zero)

typedef __nv_bfloat16 bf16;

// Scratch (static device buffers; allocation is forbidden)
__device__ float g_xzres[(size_t)BB * LL * 2 * DI];
__device__ float g_xcT[(size_t)DI * MM];
__device__ float g_sresT[(size_t)DI * MM];
__device__ float g_xdbl[(size_t)BB * LL * 96];
__device__ float g_xpart[(size_t)GG * MM * NXP];
__device__ float g_opart[(size_t)2 * MM * DM];
__device__ float g_deltaT[(size_t)DI * MM];
__device__ float g_hend[(size_t)BB * DI * GG * NS];
__device__ float g_hcar[(size_t)BB * DI * GG * NS];
__device__ float g_sdl[(size_t)BB * DI * GG];
__device__ bf16 g_xh[(size_t)MM * DM],    g_xl[(size_t)MM * DM];
__device__ bf16 g_Winh[(size_t)2 * DI * DM], g_Winl[(size_t)2 * DI * DM];
__device__ bf16 g_Wouth[(size_t)DM * DI], g_Woutl[(size_t)DM * DI];
__device__ bf16 g_Wxh[(size_t)NXP * DI],  g_Wxl[(size_t)NXP * DI];   // rows 96..127 zero
__device__ bf16 g_Wdth[(size_t)DI * DTR], g_Wdtl[(size_t)DI * DTR];
__device__ bf16 g_xch[(size_t)MM * DI],   g_xcl[(size_t)MM * DI];
__device__ bf16 g_dth[(size_t)MM * DTR],  g_dtl[(size_t)MM * DTR];
__device__ bf16 g_yh[(size_t)MM * DI],    g_yl[(size_t)MM * DI];

__device__ __forceinline__ float softplusf(float v)
{
    return (v > 20.f) ? v : log1pf(expf(v));
}

// ===========================================================================
// Fused bf16 Dekker split of ALL GEMM operands in one launch.
// Segment lengths in float4 units (element counts / 4):
//   x: MM*DM | W_in: 2*DI*DM | W_out: DM*DI | W_dt: DI*DTR | W_x: 96*DI
// W_x splits into the first 96 rows of the zero-padded [128, DI] buffers.
// ===========================================================================
#define SEG0 ((MM * DM) / 4)
#define SEG1 (SEG0 + (2 * DI * DM) / 4)
#define SEG2 (SEG1 + (DM * DI) / 4)
#define SEG3 (SEG2 + (DI * DTR) / 4)
#define SEG4 (SEG3 + (96 * DI) / 4)

__device__ __forceinline__ void split4(float4 v, uint2& h4, uint2& l4)
{
    bf16 h0 = __float2bfloat16(v.x), h1 = __float2bfloat16(v.y);
    bf16 h2 = __float2bfloat16(v.z), h3 = __float2bfloat16(v.w);
    bf16 l0 = __float2bfloat16(v.x - __bfloat162float(h0));
    bf16 l1 = __float2bfloat16(v.y - __bfloat162float(h1));
    bf16 l2 = __float2bfloat16(v.z - __bfloat162float(h2));
    bf16 l3 = __float2bfloat16(v.w - __bfloat162float(h3));
    __nv_bfloat162 hh0(h0, h1), hh1(h2, h3), ll0(l0, l1), ll1(l2, l3);
    h4.x = *(uint32_t*)&hh0; h4.y = *(uint32_t*)&hh1;
    l4.x = *(uint32_t*)&ll0; l4.y = *(uint32_t*)&ll1;
}

__global__ void split_all(const float* __restrict__ x,
                          const float* __restrict__ Wi,
                          const float* __restrict__ Wo,
                          const float* __restrict__ Wd,
                          const float* __restrict__ Wx,
                          bf16* __restrict__ xh, bf16* __restrict__ xl,
                          bf16* __restrict__ Wih, bf16* __restrict__ Wil,
                          bf16* __restrict__ Woh, bf16* __restrict__ Wol,
                          bf16* __restrict__ Wdh, bf16* __restrict__ Wdl,
                          bf16* __restrict__ Wxh, bf16* __restrict__ Wxl)
{
    int i = blockIdx.x * blockDim.x + threadIdx.x;   // float4 index
    if (i >= SEG4) return;
    const float4* src;
    uint2 *hi, *lo;
    int j;
    if (i < SEG0)      { j = i;        src = (const float4*)x;  hi = (uint2*)xh;  lo = (uint2*)xl; }
    else if (i < SEG1) { j = i - SEG0; src = (const float4*)Wi; hi = (uint2*)Wih; lo = (uint2*)Wil; }
    else if (i < SEG2) { j = i - SEG1; src = (const float4*)Wo; hi = (uint2*)Woh; lo = (uint2*)Wol; }
    else if (i < SEG3) { j = i - SEG2; src = (const float4*)Wd; hi = (uint2*)Wdh; lo = (uint2*)Wdl; }
    else               { j = i - SEG3; src = (const float4*)Wx; hi = (uint2*)Wxh; lo = (uint2*)Wxl; }
    uint2 h4, l4;
    split4(src[j], h4, l4);
    hi[j] = h4;
    lo[j] = l4;
}

#define CP16(dst_u32, src_ptr) \
    asm volatile("cp.async.cg.shared.global [%0], [%1], 16;" :: "r"(dst_u32), "l"(src_ptr))

__device__ __forceinline__ void mma_bf16(float* d, const uint32_t* a, const uint32_t* b)
{
    asm volatile(
        "mma.sync.aligned.m16n8k16.row.col.f32.bf16.bf16.f32 "
        "{%0,%1,%2,%3}, {%4,%5,%6,%7}, {%8,%9}, {%0,%1,%2,%3};"
        : "+f"(d[0]), "+f"(d[1]), "+f"(d[2]), "+f"(d[3])
        : "r"(a[0]), "r"(a[1]), "r"(a[2]), "r"(a[3]), "r"(b[0]), "r"(b[1]));
}

__device__ __forceinline__ void ldsm4(uint32_t& r0, uint32_t& r1,
                                      uint32_t& r2, uint32_t& r3, uint32_t addr)
{
    asm volatile("ldmatrix.sync.aligned.m8n8.x4.shared.b16 {%0,%1,%2,%3}, [%4];"
                 : "=r"(r0), "=r"(r1), "=r"(r2), "=r"(r3) : "r"(addr));
}

// ===========================================================================
// mma.sync bf16x3 GEMM: C[M,N] = A[M,K] @ B[N,K]^T, fp32 out.
// 128x128 tile, 8 warps of 64x32, BK=32, 2-stage cp.async, ldmatrix,
// 2 CTAs/SM. MODE 0: plain store. MODE 1: softplus(acc+bias) transposed.
// SPLITK>1: blockIdx.z K-slice, C += z*zstride.
// ===========================================================================
#define BM3 128
#define BN3 128
#define BK3 32
#define ROWB 80
#define TSB (128 * ROWB)

template <int MODE, int SPLITK>
__global__ __launch_bounds__(256, 2)
void gemm_bf16x3(const bf16* __restrict__ Ahg, const bf16* __restrict__ Alg,
                 const bf16* __restrict__ Bhg, const bf16* __restrict__ Blg,
                 float* __restrict__ C, int ldc, int ldk, int kcount,
                 size_t zstride, const float* __restrict__ bias)
{
    extern __shared__ char sm[];
    const uint32_t sbase = (uint32_t)__cvta_generic_to_shared(sm);
    const uint32_t oAh = 0, oAl = 2 * TSB, oBh = 4 * TSB, oBl = 6 * TSB;

    const int tid  = threadIdx.x;
    const int warp = tid >> 5, lane = tid & 31;
    const int wm = (warp & 1) * 64;
    const int wn = (warp >> 1) * 32;
    const int g  = lane >> 2;
    const int tg = lane & 3;
    const int row0 = blockIdx.y * BM3;
    const int col0 = blockIdx.x * BN3;
    const int kbeg = (SPLITK > 1) ? blockIdx.z * kcount : 0;
    if (SPLITK > 1) C += (size_t)blockIdx.z * zstride;

    const int lrow = tid >> 1;
    const int lcb  = (tid & 1) * 16;

    const int lrA  = lane & 15;
    const int lkA  = (lane >> 4) * 16;
    const int lrB  = (lane & 7) + ((lane >> 4) << 3);
    const int lkB  = ((lane >> 3) & 1) * 16;

    float acc[4][4][4] = {};
    const int iters = kcount / BK3;

    auto load_tile = [&](int tile) {
        const int s = tile & 1;
        const int k0 = kbeg + tile * BK3;
        {
            const bf16* p = Ahg + (size_t)(row0 + lrow) * ldk + k0 + lcb;
            uint32_t d = sbase + oAh + s * TSB + lrow * ROWB + lcb * 2;
            CP16(d, p); CP16(d + 16, p + 8);
        }
        {
            const bf16* p = Alg + (size_t)(row0 + lrow) * ldk + k0 + lcb;
            uint32_t d = sbase + oAl + s * TSB + lrow * ROWB + lcb * 2;
            CP16(d, p); CP16(d + 16, p + 8);
        }
        {
            const bf16* p = Bhg + (size_t)(col0 + lrow) * ldk + k0 + lcb;
            uint32_t d = sbase + oBh + s * TSB + lrow * ROWB + lcb * 2;
            CP16(d, p); CP16(d + 16, p + 8);
        }
        {
            const bf16* p = Blg + (size_t)(col0 + lrow) * ldk + k0 + lcb;
            uint32_t d = sbase + oBl + s * TSB + lrow * ROWB + lcb * 2;
            CP16(d, p); CP16(d + 16, p + 8);
        }
        asm volatile("cp.async.commit_group;");
    };

    load_tile(0);

    for (int it = 0; it < iters; ++it) {
        if (it + 1 < iters) {
            load_tile(it + 1);
            asm volatile("cp.async.wait_group 1;");
        } else {
            asm volatile("cp.async.wait_group 0;");
        }
        __syncthreads();

        const int s = it & 1;
        const uint32_t bAh = sbase + oAh + s * TSB;
        const uint32_t bAl = sbase + oAl + s * TSB;
        const uint32_t bBh = sbase + oBh + s * TSB;
        const uint32_t bBl = sbase + oBl + s * TSB;

#pragma unroll
        for (int ks = 0; ks < 2; ++ks) {
            const int kb = ks * 32;
            uint32_t ah[4][4], al[4][4], bh[4][2], bl[4][2];
#pragma unroll
            for (int mt = 0; mt < 4; ++mt) {
                const uint32_t ra = (wm + mt * 16 + lrA) * ROWB + kb + lkA;
                ldsm4(ah[mt][0], ah[mt][1], ah[mt][2], ah[mt][3], bAh + ra);
                ldsm4(al[mt][0], al[mt][1], al[mt][2], al[mt][3], bAl + ra);
            }
#pragma unroll
            for (int np = 0; np < 2; ++np) {
                const uint32_t rb = (wn + np * 16 + lrB) * ROWB + kb + lkB;
                ldsm4(bh[2*np][0], bh[2*np][1], bh[2*np+1][0], bh[2*np+1][1], bBh + rb);
                ldsm4(bl[2*np][0], bl[2*np][1], bl[2*np+1][0], bl[2*np+1][1], bBl + rb);
            }
#pragma unroll
            for (int mt = 0; mt < 4; ++mt)
#pragma unroll
                for (int nt = 0; nt < 4; ++nt) {
                    mma_bf16(acc[mt][nt], al[mt], bh[nt]);
                    mma_bf16(acc[mt][nt], ah[mt], bl[nt]);
                    mma_bf16(acc[mt][nt], ah[mt], bh[nt]);
                }
        }
        __syncthreads();
    }

    if (MODE == 0) {
#pragma unroll
        for (int mt = 0; mt < 4; ++mt) {
#pragma unroll
            for (int nt = 0; nt < 4; ++nt) {
                const int gr = row0 + wm + mt * 16 + g;
                const int gc = col0 + wn + nt * 8 + tg * 2;
                *(float2*)&C[(size_t)gr * ldc + gc] =
                    make_float2(acc[mt][nt][0], acc[mt][nt][1]);
                *(float2*)&C[(size_t)(gr + 8) * ldc + gc] =
                    make_float2(acc[mt][nt][2], acc[mt][nt][3]);
            }
        }
    } else {
        // softplus(acc + bias[col]) -> smem tile -> transposed coalesced store
        float (*st)[133] = (float(*)[133])sm;
#pragma unroll
        for (int mt = 0; mt < 4; ++mt) {
#pragma unroll
            for (int nt = 0; nt < 4; ++nt) {
                const int lr = wm + mt * 16 + g;
                const int lc = wn + nt * 8 + tg * 2;
                const float b0 = bias[col0 + lc];
                const float b1 = bias[col0 + lc + 1];
                st[lr][lc]          = softplusf(acc[mt][nt][0] + b0);
                st[lr][lc + 1]      = softplusf(acc[mt][nt][1] + b1);
                st[lr + 8][lc]      = softplusf(acc[mt][nt][2] + b0);
                st[lr + 8][lc + 1]  = softplusf(acc[mt][nt][3] + b1);
            }
        }
        __syncthreads();
#pragma unroll
        for (int ci = 0; ci < 16; ++ci) {
            const int c = warp + ci * 8;
            float* dst = C + (size_t)(col0 + c) * MM + row0;
#pragma unroll
            for (int k = 0; k < 4; ++k)
                dst[32 * k + lane] = st[32 * k + lane][c];
        }
    }
}

// ---------------------------------------------------------------------------
// out_proj split-K reduce (float4): out = part0 + part1
// ---------------------------------------------------------------------------
__global__ void reduce_out(const float* __restrict__ part,
                           float* __restrict__ out, int n4)
{
    int i = blockIdx.x * blockDim.x + threadIdx.x;
    if (i >= n4) return;
    const float4* p0 = (const float4*)part;
    const float4* p1 = p0 + n4;
    float4 a = p0[i], b = p1[i];
    ((float4*)out)[i] = make_float4(a.x + b.x, a.y + b.y, a.z + b.z, a.w + b.w);
}

// x_proj reduce over [z][M][NXP] partials -> xdbl[M,96];
// also emits bf16 hi/lo split of the first 64 cols (dt input).
__global__ void reduce_sk(const float* __restrict__ part,
                          float* __restrict__ out,
                          bf16* __restrict__ dth, bf16* __restrict__ dtl, int n)
{
    int i = blockIdx.x * blockDim.x + threadIdx.x;
    if (i >= n) return;
    int row = i / 96;
    int col = i % 96;
    float s = 0.f;
#pragma unroll
    for (int z = 0; z < GG; z++)
        s += part[(size_t)z * MM * NXP + (size_t)row * NXP + col];
    out[i] = s;
    if (col < DTR) {
        bf16 h = __float2bfloat16(s);
        dth[(size_t)row * DTR + col] = h;
        dtl[(size_t)row * DTR + col] = __float2bfloat16(s - __bfloat162float(h));
    }
}

// ---------------------------------------------------------------------------
// Causal depthwise conv1d (k=4) + SiLU, tiled.
// Emits xc as bf16 hi/lo (row-major, for x_proj), xc_T and silu(res)_T (fp32).
// ---------------------------------------------------------------------------
__global__ __launch_bounds__(256)
void conv_silu_tr(const float* __restrict__ xzres,
                  const float* __restrict__ w,
                  const float* __restrict__ cb,
                  bf16* __restrict__ xch, bf16* __restrict__ xcl,
                  float* __restrict__ xcT,
                  float* __restrict__ sresT)
{
    __shared__ float sxz[36][33];
    __shared__ float sout[32][33];
    __shared__ float sres[32][33];

    const int d0 = blockIdx.x * 32;
    const int t0 = blockIdx.y * 32;
    const int b  = blockIdx.z;
    const int lane = threadIdx.x & 31;
    const int ty   = threadIdx.x >> 5;
    const size_t rs = 2 * DI;

    for (int r = ty; r < 35; r += 8) {
        int t = t0 - 3 + r;
        float v = 0.f;
        if (t >= 0) v = xzres[((size_t)(b * LL + t)) * rs + d0 + lane];
        sxz[r][lane] = v;
    }
    for (int r = ty; r < 32; r += 8) {
        int t = t0 + r;
        float v = xzres[((size_t)(b * LL + t)) * rs + DI + d0 + lane];
        sres[r][lane] = v / (1.f + __expf(-v));
    }
    __syncthreads();

    float wv[KC];
#pragma unroll
    for (int i = 0; i < KC; i++) wv[i] = w[(d0 + lane) * KC + i];
    const float bias = cb[d0 + lane];

    for (int r = ty; r < 32; r += 8) {
        float acc = bias;
#pragma unroll
        for (int i = 0; i < KC; i++)
            acc = fmaf(sxz[r + i][lane], wv[i], acc);
        float s = acc / (1.f + __expf(-acc));
        sout[r][lane] = s;
        const size_t o = ((size_t)(b * LL + t0 + r)) * DI + d0 + lane;
        bf16 hb = __float2bfloat16(s);
        xch[o] = hb;
        xcl[o] = __float2bfloat16(s - __bfloat162float(hb));
    }
    __syncthreads();

    for (int r = ty; r < 32; r += 8) {
        xcT  [((size_t)(d0 + r)) * MM + b * LL + t0 + lane] = sout[lane][r];
        sresT[((size_t)(d0 + r)) * MM + b * LL + t0 + lane] = sres[lane][r];
    }
}

// ---------------------------------------------------------------------------
// Block-parallel selective scan, G=8 groups of 128 t (3 passes).
// ---------------------------------------------------------------------------
__global__ __launch_bounds__(256)
void scan_pass1(const float* __restrict__ deltaT,
                const float* __restrict__ xcT,
                const float* __restrict__ xdbl,
                const float* __restrict__ A_log,
                float* __restrict__ hend, float* __restrict__ sdlv)
{
    __shared__ float sB[GT][16];

    const int bx = blockIdx.x;
    const int dchunk = bx & 63;
    const int g = (bx >> 6) & (GG - 1);
    const int b = bx >> 9;
    const int n8 = threadIdx.x & 7;
    const int d = dchunk * 32 + (threadIdx.x >> 3);

    const float* xdB = xdbl + (size_t)b * LL * 96 + DTR;
    for (int i = threadIdx.x; i < GT * 16; i += 256) {
        int tt = i >> 4, c = i & 15;
        sB[tt][c] = xdB[(size_t)(g * GT + tt) * 96 + c];
    }
    __syncthreads();

    const float Adn0 = -expf(A_log[d * NS + n8]);
    const float Adn1 = -expf(A_log[d * NS + n8 + 8]);
    float h0 = 0.f, h1 = 0.f, sdl = 0.f;

    const size_t base = (size_t)d * MM + (size_t)b * LL + g * GT;
    const float4* dT4 = (const float4*)(deltaT + base);
    const float4* uT4 = (const float4*)(xcT + base);

    for (int tb = 0; tb < GT; tb += 4) {
        float4 dl4 = dT4[tb >> 2];
        float4 u4  = uT4[tb >> 2];
        float dls[4] = {dl4.x, dl4.y, dl4.z, dl4.w};
        float us[4]  = {u4.x,  u4.y,  u4.z,  u4.w};
#pragma unroll
        for (int j = 0; j < 4; j++) {
            const int tt = tb + j;
            float dl = dls[j];
            sdl += dl;
            float db = dl * us[j];
            h0 = fmaf(__expf(dl * Adn0), h0, db * sB[tt][n8]);
            h1 = fmaf(__expf(dl * Adn1), h1, db * sB[tt][n8 + 8]);
        }
    }
    const size_t o = (((size_t)b * DI + d) * GG + g) * NS;
    hend[o + n8] = h0;
    hend[o + n8 + 8] = h1;
    if (n8 == 0) sdlv[((size_t)b * DI + d) * GG + g] = sdl;
}

__global__ void scan_pass2(const float* __restrict__ hend,
                           const float* __restrict__ sdlv,
                           const float* __restrict__ A_log,
                           float* __restrict__ hcar)
{
    int tid = blockIdx.x * blockDim.x + threadIdx.x;
    int n = tid & 15;
    int d = (tid >> 4) & (DI - 1);
    int b = tid >> 15;
    const float Adn = -expf(A_log[d * NS + n]);
    float H = 0.f;
    const size_t ob = ((size_t)b * DI + d) * GG;
    for (int g = 0; g < GG; g++) {
        hcar[(ob + g) * NS + n] = H;
        H = fmaf(__expf(Adn * sdlv[ob + g]), H, hend[(ob + g) * NS + n]);
    }
}

__global__ __launch_bounds__(256)
void scan_pass3(const float* __restrict__ deltaT,
                const float* __restrict__ xcT,
                const float* __restrict__ sresT,
                const float* __restrict__ xdbl,
                const float* __restrict__ A_log,
                const float* __restrict__ Dp,
                const float* __restrict__ hcar,
                bf16* __restrict__ yh, bf16* __restrict__ yl)
{
    __shared__ float sBC[GT][32];

    const int bx = blockIdx.x;
    const int dchunk = bx & 63;
    const int g = (bx >> 6) & (GG - 1);
    const int b = bx >> 9;
    const int n8 = threadIdx.x & 7;
    const int d = dchunk * 32 + (threadIdx.x >> 3);

    const float* xdBC = xdbl + (size_t)b * LL * 96 + DTR;
    for (int i = threadIdx.x; i < GT * 32; i += 256) {
        int tt = i >> 5, c = i & 31;
        sBC[tt][c] = xdBC[(size_t)(g * GT + tt) * 96 + c];
    }
    __syncthreads();

    const float Adn0 = -expf(A_log[d * NS + n8]);
    const float Adn1 = -expf(A_log[d * NS + n8 + 8]);
    const float Dd = Dp[d];
    const size_t oc = (((size_t)b * DI + d) * GG + g) * NS;
    float h0 = hcar[oc + n8];
    float h1 = hcar[oc + n8 + 8];

    const size_t base = (size_t)d * MM + (size_t)b * LL + g * GT;
    const float4* dT4 = (const float4*)(deltaT + base);
    const float4* uT4 = (const float4*)(xcT + base);
    const float4* sT4 = (const float4*)(sresT + base);
    const size_t ybase = ((size_t)b * LL + g * GT) * DI + d;

    for (int tb = 0; tb < GT; tb += 4) {
        float4 dl4 = dT4[tb >> 2];
        float4 u4  = uT4[tb >> 2];
        float4 s4  = sT4[tb >> 2];
        float dls[4] = {dl4.x, dl4.y, dl4.z, dl4.w};
        float us[4]  = {u4.x,  u4.y,  u4.z,  u4.w};
        float ss[4]  = {s4.x,  s4.y,  s4.z,  s4.w};
        float yp[4];

#pragma unroll
        for (int j = 0; j < 4; j++) {
            const int tt = tb + j;
            float Bv0 = sBC[tt][n8];
            float Bv1 = sBC[tt][n8 + 8];
            float Cv0 = sBC[tt][n8 + 16];
            float Cv1 = sBC[tt][n8 + 24];
            float dl = dls[j];
            float e0 = __expf(dl * Adn0);
            float e1 = __expf(dl * Adn1);
            float db = dl * us[j];
            h0 = fmaf(e0, h0, db * Bv0);
            h1 = fmaf(e1, h1, db * Bv1);
            yp[j] = fmaf(h0, Cv0, h1 * Cv1);
        }

#pragma unroll
        for (int j = 0; j < 4; j++) yp[j] += __shfl_xor_sync(0xffffffffu, yp[j], 4);
#pragma unroll
        for (int j = 0; j < 4; j++) yp[j] += __shfl_xor_sync(0xffffffffu, yp[j], 2);
#pragma unroll
        for (int j = 0; j < 4; j++) yp[j] += __shfl_xor_sync(0xffffffffu, yp[j], 1);

        if (n8 == 0) {
#pragma unroll
            for (int j = 0; j < 4; j++) {
                float w = (yp[j] + us[j] * Dd) * ss[j];
                bf16 hb = __float2bfloat16(w);
                const size_t off = ybase + (size_t)(tb + j) * DI;
                yh[off] = hb;
                yl[off] = __float2bfloat16(w - __bfloat162float(hb));
            }
        }
    }
}

// ---------------------------------------------------------------------------
extern "C" void kernel_launch(void* const* d_in, const int* in_sizes, int n_in,
                              void* d_out, int out_size)
{
    const float* x      = (const float*)d_in[0];
    const float* W_in   = (const float*)d_in[1];
    const float* conv_w = (const float*)d_in[2];
    const float* conv_b = (const float*)d_in[3];
    const float* W_x    = (const float*)d_in[4];
    const float* W_dt   = (const float*)d_in[5];
    const float* b_dt   = (const float*)d_in[6];
    const float* A_log  = (const float*)d_in[7];
    const float* Dp     = (const float*)d_in[8];
    const float* W_out  = (const float*)d_in[9];
    float* out = (float*)d_out;

    float *p_xzres, *p_xcT, *p_sresT, *p_xdbl, *p_xpart, *p_opart, *p_deltaT;
    float *p_hend, *p_hcar, *p_sdl;
    bf16 *p_xh, *p_xl, *p_Winh, *p_Winl, *p_Wouth, *p_Woutl;
    bf16 *p_Wxh, *p_Wxl, *p_Wdth, *p_Wdtl, *p_xch, *p_xcl, *p_dth, *p_dtl, *p_yh, *p_yl;
    cudaGetSymbolAddress((void**)&p_xzres,  g_xzres);
    cudaGetSymbolAddress((void**)&p_xcT,    g_xcT);
    cudaGetSymbolAddress((void**)&p_sresT,  g_sresT);
    cudaGetSymbolAddress((void**)&p_xdbl,   g_xdbl);
    cudaGetSymbolAddress((void**)&p_xpart,  g_xpart);
    cudaGetSymbolAddress((void**)&p_opart,  g_opart);
    cudaGetSymbolAddress((void**)&p_deltaT, g_deltaT);
    cudaGetSymbolAddress((void**)&p_hend,   g_hend);
    cudaGetSymbolAddress((void**)&p_hcar,   g_hcar);
    cudaGetSymbolAddress((void**)&p_sdl,    g_sdl);
    cudaGetSymbolAddress((void**)&p_xh,     g_xh);
    cudaGetSymbolAddress((void**)&p_xl,     g_xl);
    cudaGetSymbolAddress((void**)&p_Winh,   g_Winh);
    cudaGetSymbolAddress((void**)&p_Winl,   g_Winl);
    cudaGetSymbolAddress((void**)&p_Wouth,  g_Wouth);
    cudaGetSymbolAddress((void**)&p_Woutl,  g_Woutl);
    cudaGetSymbolAddress((void**)&p_Wxh,    g_Wxh);
    cudaGetSymbolAddress((void**)&p_Wxl,    g_Wxl);
    cudaGetSymbolAddress((void**)&p_Wdth,   g_Wdth);
    cudaGetSymbolAddress((void**)&p_Wdtl,   g_Wdtl);
    cudaGetSymbolAddress((void**)&p_xch,    g_xch);
    cudaGetSymbolAddress((void**)&p_xcl,    g_xcl);
    cudaGetSymbolAddress((void**)&p_dth,    g_dth);
    cudaGetSymbolAddress((void**)&p_dtl,    g_dtl);
    cudaGetSymbolAddress((void**)&p_yh,     g_yh);
    cudaGetSymbolAddress((void**)&p_yl,     g_yl);

    cudaFuncSetAttribute(gemm_bf16x3<0, 1>,
                         cudaFuncAttributeMaxDynamicSharedMemorySize, 8 * TSB);
    cudaFuncSetAttribute(gemm_bf16x3<0, 2>,
                         cudaFuncAttributeMaxDynamicSharedMemorySize, 8 * TSB);
    cudaFuncSetAttribute(gemm_bf16x3<0, 8>,
                         cudaFuncAttributeMaxDynamicSharedMemorySize, 8 * TSB);
    cudaFuncSetAttribute(gemm_bf16x3<1, 1>,
                         cudaFuncAttributeMaxDynamicSharedMemorySize, 8 * TSB);

    // 0) fused bf16 hi/lo split of x, W_in, W_out, W_dt, W_x (one launch)
    split_all<<<(SEG4 + 255) / 256, 256>>>(
        x, W_in, W_out, W_dt, W_x,
        p_xh, p_xl, p_Winh, p_Winl, p_Wouth, p_Woutl,
        p_Wdth, p_Wdtl, p_Wxh, p_Wxl);

    // 1) in_proj (bf16x3): xzres[M,4096] = x @ W_in^T
    gemm_bf16x3<0, 1><<<dim3(2 * DI / BN3, MM / BM3), 256, 8 * TSB>>>(
        p_xh, p_xl, p_Winh, p_Winl, p_xzres, 2 * DI, DM, DM, 0, nullptr);

    // 2) causal conv + silu -> xc (bf16 hi/lo) + xcT + sresT
    conv_silu_tr<<<dim3(DI / 32, LL / 32, BB), 256>>>(
        p_xzres, conv_w, conv_b, p_xch, p_xcl, p_xcT, p_sresT);

    // 3) x_proj (bf16x3, split-K x8, padded N=128) + reduce (fused dt split)
    gemm_bf16x3<0, 8><<<dim3(1, MM / BM3, GG), 256, 8 * TSB>>>(
        p_xch, p_xcl, p_Wxh, p_Wxl, p_xpart, NXP, DI, DI / GG,
        (size_t)MM * NXP, nullptr);
    reduce_sk<<<(MM * 96) / 256, 256>>>(p_xpart, p_xdbl, p_dth, p_dtl, MM * 96);

    // 4) dt_proj (bf16x3, fused softplus + transposed store): deltaT[DI,M]
    gemm_bf16x3<1, 1><<<dim3(DI / BN3, MM / BM3), 256, 8 * TSB>>>(
        p_dth, p_dtl, p_Wdth, p_Wdtl, p_deltaT, 0, DTR, DTR, 0, b_dt);

    // 5) block-parallel selective scan (3 passes) -> y (bf16 hi/lo)
    scan_pass1<<<BB * GG * (DI / 32), 256>>>(
        p_deltaT, p_xcT, p_xdbl, A_log, p_hend, p_sdl);
    scan_pass2<<<(BB * DI * NS) / 256, 256>>>(p_hend, p_sdl, A_log, p_hcar);
    scan_pass3<<<BB * GG * (DI / 32), 256>>>(
        p_deltaT, p_xcT, p_sresT, p_xdbl, A_log, Dp, p_hcar, p_yh, p_yl);

    // 6) out_proj (bf16x3, split-K x2) + reduce -> out
    gemm_bf16x3<0, 2><<<dim3(DM / BN3, MM / BM3, 2), 256, 8 * TSB>>>(
        p_yh, p_yl, p_Wouth, p_Woutl, p_opart, DM, DI, DI / 2,
        (size_t)MM * DM, nullptr);
    reduce_out<<<(MM * DM / 4) / 256, 256>>>(p_opart, out, MM * DM / 4);
}

// round 14
// speedup vs baseline: 1.5256x; 1.5256x over previous
#include <cuda_runtime.h>
#include <cuda_bf16.h>
#include <cstdint>

// Problem dims
#define BB 2
#define LL 1024
#define DM 1024
#define DI 2048
#define NS 16
#define DTR 64
#define KC 4
#define MM (BB * LL)   // 2048 token rows
#define GG 8           // scan groups / split-K factor
#define GT (LL / GG)   // 128 t per group
#define NXP 128        // x_proj padded N (96 real + 32 zero)

typedef __nv_bfloat16 bf16;

// Scratch (static device buffers; allocation is forbidden)
__device__ float g_xzres[(size_t)BB * LL * 2 * DI];
__device__ float g_xc[(size_t)BB * LL * DI];          // conv+silu fp32 (row-major)
__device__ float g_xcT[(size_t)DI * MM];
__device__ float g_sresT[(size_t)DI * MM];
__device__ float g_xdbl[(size_t)BB * LL * 96];
__device__ float g_xpart[(size_t)GG * MM * NXP];
__device__ float g_opart[(size_t)2 * MM * DM];
__device__ float g_deltaT[(size_t)DI * MM];
__device__ float g_hend[(size_t)BB * DI * GG * NS];
__device__ float g_hcar[(size_t)BB * DI * GG * NS];
__device__ float g_sdl[(size_t)BB * DI * GG];
__device__ bf16 g_xh[(size_t)MM * DM],    g_xl[(size_t)MM * DM];
__device__ bf16 g_Winh[(size_t)2 * DI * DM], g_Winl[(size_t)2 * DI * DM];
__device__ bf16 g_Wouth[(size_t)DM * DI], g_Woutl[(size_t)DM * DI];
__device__ bf16 g_Wxh[(size_t)NXP * DI],  g_Wxl[(size_t)NXP * DI];   // rows 96..127 zero
__device__ bf16 g_Wdth[(size_t)DI * DTR], g_Wdtl[(size_t)DI * DTR];
__device__ bf16 g_xch[(size_t)MM * DI],   g_xcl[(size_t)MM * DI];
__device__ bf16 g_dth[(size_t)MM * DTR],  g_dtl[(size_t)MM * DTR];
__device__ bf16 g_yh[(size_t)MM * DI],    g_yl[(size_t)MM * DI];

__device__ __forceinline__ float softplusf(float v)
{
    return (v > 20.f) ? v : log1pf(expf(v));
}

// ===========================================================================
// Fused bf16 Dekker split of GEMM weight/input operands (one launch).
// Segment lengths in float4 units (element counts / 4).
// ===========================================================================
#define SEG0 ((MM * DM) / 4)
#define SEG1 (SEG0 + (2 * DI * DM) / 4)
#define SEG2 (SEG1 + (DM * DI) / 4)
#define SEG3 (SEG2 + (DI * DTR) / 4)
#define SEG4 (SEG3 + (96 * DI) / 4)

__device__ __forceinline__ void split4(float4 v, uint2& h4, uint2& l4)
{
    bf16 h0 = __float2bfloat16(v.x), h1 = __float2bfloat16(v.y);
    bf16 h2 = __float2bfloat16(v.z), h3 = __float2bfloat16(v.w);
    bf16 l0 = __float2bfloat16(v.x - __bfloat162float(h0));
    bf16 l1 = __float2bfloat16(v.y - __bfloat162float(h1));
    bf16 l2 = __float2bfloat16(v.z - __bfloat162float(h2));
    bf16 l3 = __float2bfloat16(v.w - __bfloat162float(h3));
    __nv_bfloat162 hh0(h0, h1), hh1(h2, h3), ll0(l0, l1), ll1(l2, l3);
    h4.x = *(uint32_t*)&hh0; h4.y = *(uint32_t*)&hh1;
    l4.x = *(uint32_t*)&ll0; l4.y = *(uint32_t*)&ll1;
}

__global__ void split_all(const float* __restrict__ x,
                          const float* __restrict__ Wi,
                          const float* __restrict__ Wo,
                          const float* __restrict__ Wd,
                          const float* __restrict__ Wx,
                          bf16* __restrict__ xh, bf16* __restrict__ xl,
                          bf16* __restrict__ Wih, bf16* __restrict__ Wil,
                          bf16* __restrict__ Woh, bf16* __restrict__ Wol,
                          bf16* __restrict__ Wdh, bf16* __restrict__ Wdl,
                          bf16* __restrict__ Wxh, bf16* __restrict__ Wxl)
{
    int i = blockIdx.x * blockDim.x + threadIdx.x;   // float4 index
    if (i >= SEG4) return;
    const float4* src;
    uint2 *hi, *lo;
    int j;
    if (i < SEG0)      { j = i;        src = (const float4*)x;  hi = (uint2*)xh;  lo = (uint2*)xl; }
    else if (i < SEG1) { j = i - SEG0; src = (const float4*)Wi; hi = (uint2*)Wih; lo = (uint2*)Wil; }
    else if (i < SEG2) { j = i - SEG1; src = (const float4*)Wo; hi = (uint2*)Woh; lo = (uint2*)Wol; }
    else if (i < SEG3) { j = i - SEG2; src = (const float4*)Wd; hi = (uint2*)Wdh; lo = (uint2*)Wdl; }
    else               { j = i - SEG3; src = (const float4*)Wx; hi = (uint2*)Wxh; lo = (uint2*)Wxl; }
    uint2 h4, l4;
    split4(src[j], h4, l4);
    hi[j] = h4;
    lo[j] = l4;
}

// Standalone bf16 split of xc (keeps the conv kernel byte-identical to the
// validated R12 version).
__global__ void split_xc(const float* __restrict__ src,
                         bf16* __restrict__ hi, bf16* __restrict__ lo, int n4)
{
    int i = blockIdx.x * blockDim.x + threadIdx.x;
    if (i >= n4) return;
    uint2 h4, l4;
    split4(((const float4*)src)[i], h4, l4);
    ((uint2*)hi)[i] = h4;
    ((uint2*)lo)[i] = l4;
}

#define CP16(dst_u32, src_ptr) \
    asm volatile("cp.async.cg.shared.global [%0], [%1], 16;" :: "r"(dst_u32), "l"(src_ptr))

__device__ __forceinline__ void mma_bf16(float* d, const uint32_t* a, const uint32_t* b)
{
    asm volatile(
        "mma.sync.aligned.m16n8k16.row.col.f32.bf16.bf16.f32 "
        "{%0,%1,%2,%3}, {%4,%5,%6,%7}, {%8,%9}, {%0,%1,%2,%3};"
        : "+f"(d[0]), "+f"(d[1]), "+f"(d[2]), "+f"(d[3])
        : "r"(a[0]), "r"(a[1]), "r"(a[2]), "r"(a[3]), "r"(b[0]), "r"(b[1]));
}

__device__ __forceinline__ void ldsm4(uint32_t& r0, uint32_t& r1,
                                      uint32_t& r2, uint32_t& r3, uint32_t addr)
{
    asm volatile("ldmatrix.sync.aligned.m8n8.x4.shared.b16 {%0,%1,%2,%3}, [%4];"
                 : "=r"(r0), "=r"(r1), "=r"(r2), "=r"(r3) : "r"(addr));
}

// ===========================================================================
// mma.sync bf16x3 GEMM: C[M,N] = A[M,K] @ B[N,K]^T, fp32 out.
// 128x128 tile, 8 warps of 64x32, BK=32, 2-stage cp.async, ldmatrix,
// 2 CTAs/SM. MODE 0: plain store. MODE 1: softplus(acc+bias) transposed.
// SPLITK>1: blockIdx.z K-slice, C += z*zstride.
// ===========================================================================
#define BM3 128
#define BN3 128
#define BK3 32
#define ROWB 80
#define TSB (128 * ROWB)

template <int MODE, int SPLITK>
__global__ __launch_bounds__(256, 2)
void gemm_bf16x3(const bf16* __restrict__ Ahg, const bf16* __restrict__ Alg,
                 const bf16* __restrict__ Bhg, const bf16* __restrict__ Blg,
                 float* __restrict__ C, int ldc, int ldk, int kcount,
                 size_t zstride, const float* __restrict__ bias)
{
    extern __shared__ char sm[];
    const uint32_t sbase = (uint32_t)__cvta_generic_to_shared(sm);
    const uint32_t oAh = 0, oAl = 2 * TSB, oBh = 4 * TSB, oBl = 6 * TSB;

    const int tid  = threadIdx.x;
    const int warp = tid >> 5, lane = tid & 31;
    const int wm = (warp & 1) * 64;
    const int wn = (warp >> 1) * 32;
    const int g  = lane >> 2;
    const int tg = lane & 3;
    const int row0 = blockIdx.y * BM3;
    const int col0 = blockIdx.x * BN3;
    const int kbeg = (SPLITK > 1) ? blockIdx.z * kcount : 0;
    if (SPLITK > 1) C += (size_t)blockIdx.z * zstride;

    const int lrow = tid >> 1;
    const int lcb  = (tid & 1) * 16;

    const int lrA  = lane & 15;
    const int lkA  = (lane >> 4) * 16;
    const int lrB  = (lane & 7) + ((lane >> 4) << 3);
    const int lkB  = ((lane >> 3) & 1) * 16;

    float acc[4][4][4] = {};
    const int iters = kcount / BK3;

    auto load_tile = [&](int tile) {
        const int s = tile & 1;
        const int k0 = kbeg + tile * BK3;
        {
            const bf16* p = Ahg + (size_t)(row0 + lrow) * ldk + k0 + lcb;
            uint32_t d = sbase + oAh + s * TSB + lrow * ROWB + lcb * 2;
            CP16(d, p); CP16(d + 16, p + 8);
        }
        {
            const bf16* p = Alg + (size_t)(row0 + lrow) * ldk + k0 + lcb;
            uint32_t d = sbase + oAl + s * TSB + lrow * ROWB + lcb * 2;
            CP16(d, p); CP16(d + 16, p + 8);
        }
        {
            const bf16* p = Bhg + (size_t)(col0 + lrow) * ldk + k0 + lcb;
            uint32_t d = sbase + oBh + s * TSB + lrow * ROWB + lcb * 2;
            CP16(d, p); CP16(d + 16, p + 8);
        }
        {
            const bf16* p = Blg + (size_t)(col0 + lrow) * ldk + k0 + lcb;
            uint32_t d = sbase + oBl + s * TSB + lrow * ROWB + lcb * 2;
            CP16(d, p); CP16(d + 16, p + 8);
        }
        asm volatile("cp.async.commit_group;");
    };

    load_tile(0);

    for (int it = 0; it < iters; ++it) {
        if (it + 1 < iters) {
            load_tile(it + 1);
            asm volatile("cp.async.wait_group 1;");
        } else {
            asm volatile("cp.async.wait_group 0;");
        }
        __syncthreads();

        const int s = it & 1;
        const uint32_t bAh = sbase + oAh + s * TSB;
        const uint32_t bAl = sbase + oAl + s * TSB;
        const uint32_t bBh = sbase + oBh + s * TSB;
        const uint32_t bBl = sbase + oBl + s * TSB;

#pragma unroll
        for (int ks = 0; ks < 2; ++ks) {
            const int kb = ks * 32;
            uint32_t ah[4][4], al[4][4], bh[4][2], bl[4][2];
#pragma unroll
            for (int mt = 0; mt < 4; ++mt) {
                const uint32_t ra = (wm + mt * 16 + lrA) * ROWB + kb + lkA;
                ldsm4(ah[mt][0], ah[mt][1], ah[mt][2], ah[mt][3], bAh + ra);
                ldsm4(al[mt][0], al[mt][1], al[mt][2], al[mt][3], bAl + ra);
            }
#pragma unroll
            for (int np = 0; np < 2; ++np) {
                const uint32_t rb = (wn + np * 16 + lrB) * ROWB + kb + lkB;
                ldsm4(bh[2*np][0], bh[2*np][1], bh[2*np+1][0], bh[2*np+1][1], bBh + rb);
                ldsm4(bl[2*np][0], bl[2*np][1], bl[2*np+1][0], bl[2*np+1][1], bBl + rb);
            }
#pragma unroll
            for (int mt = 0; mt < 4; ++mt)
#pragma unroll
                for (int nt = 0; nt < 4; ++nt) {
                    mma_bf16(acc[mt][nt], al[mt], bh[nt]);
                    mma_bf16(acc[mt][nt], ah[mt], bl[nt]);
                    mma_bf16(acc[mt][nt], ah[mt], bh[nt]);
                }
        }
        __syncthreads();
    }

    if (MODE == 0) {
#pragma unroll
        for (int mt = 0; mt < 4; ++mt) {
#pragma unroll
            for (int nt = 0; nt < 4; ++nt) {
                const int gr = row0 + wm + mt * 16 + g;
                const int gc = col0 + wn + nt * 8 + tg * 2;
                *(float2*)&C[(size_t)gr * ldc + gc] =
                    make_float2(acc[mt][nt][0], acc[mt][nt][1]);
                *(float2*)&C[(size_t)(gr + 8) * ldc + gc] =
                    make_float2(acc[mt][nt][2], acc[mt][nt][3]);
            }
        }
    } else {
        // softplus(acc + bias[col]) -> smem tile -> transposed coalesced store
        float (*st)[133] = (float(*)[133])sm;
#pragma unroll
        for (int mt = 0; mt < 4; ++mt) {
#pragma unroll
            for (int nt = 0; nt < 4; ++nt) {
                const int lr = wm + mt * 16 + g;
                const int lc = wn + nt * 8 + tg * 2;
                const float b0 = bias[col0 + lc];
                const float b1 = bias[col0 + lc + 1];
                st[lr][lc]          = softplusf(acc[mt][nt][0] + b0);
                st[lr][lc + 1]      = softplusf(acc[mt][nt][1] + b1);
                st[lr + 8][lc]      = softplusf(acc[mt][nt][2] + b0);
                st[lr + 8][lc + 1]  = softplusf(acc[mt][nt][3] + b1);
            }
        }
        __syncthreads();
#pragma unroll
        for (int ci = 0; ci < 16; ++ci) {
            const int c = warp + ci * 8;
            float* dst = C + (size_t)(col0 + c) * MM + row0;
#pragma unroll
            for (int k = 0; k < 4; ++k)
                dst[32 * k + lane] = st[32 * k + lane][c];
        }
    }
}

// ---------------------------------------------------------------------------
// out_proj split-K reduce (float4): out = part0 + part1
// ---------------------------------------------------------------------------
__global__ void reduce_out(const float* __restrict__ part,
                           float* __restrict__ out, int n4)
{
    int i = blockIdx.x * blockDim.x + threadIdx.x;
    if (i >= n4) return;
    const float4* p0 = (const float4*)part;
    const float4* p1 = p0 + n4;
    float4 a = p0[i], b = p1[i];
    ((float4*)out)[i] = make_float4(a.x + b.x, a.y + b.y, a.z + b.z, a.w + b.w);
}

// x_proj reduce over [z][M][NXP] partials -> xdbl[M,96];
// also emits bf16 hi/lo split of the first 64 cols (dt input).
__global__ void reduce_sk(const float* __restrict__ part,
                          float* __restrict__ out,
                          bf16* __restrict__ dth, bf16* __restrict__ dtl, int n)
{
    int i = blockIdx.x * blockDim.x + threadIdx.x;
    if (i >= n) return;
    int row = i / 96;
    int col = i % 96;
    float s = 0.f;
#pragma unroll
    for (int z = 0; z < GG; z++)
        s += part[(size_t)z * MM * NXP + (size_t)row * NXP + col];
    out[i] = s;
    if (col < DTR) {
        bf16 h = __float2bfloat16(s);
        dth[(size_t)row * DTR + col] = h;
        dtl[(size_t)row * DTR + col] = __float2bfloat16(s - __bfloat162float(h));
    }
}

// ---------------------------------------------------------------------------
// Causal depthwise conv1d (k=4) + SiLU, tiled (validated R12 version).
// Emits xc (fp32 row-major), xc_T, silu(res)_T.
// ---------------------------------------------------------------------------
__global__ __launch_bounds__(256)
void conv_silu_tr(const float* __restrict__ xzres,
                  const float* __restrict__ w,
                  const float* __restrict__ cb,
                  float* __restrict__ xc,
                  float* __restrict__ xcT,
                  float* __restrict__ sresT)
{
    __shared__ float sxz[36][33];
    __shared__ float sout[32][33];
    __shared__ float sres[32][33];

    const int d0 = blockIdx.x * 32;
    const int t0 = blockIdx.y * 32;
    const int b  = blockIdx.z;
    const int lane = threadIdx.x & 31;
    const int ty   = threadIdx.x >> 5;
    const size_t rs = 2 * DI;

    for (int r = ty; r < 35; r += 8) {
        int t = t0 - 3 + r;
        float v = 0.f;
        if (t >= 0) v = xzres[((size_t)(b * LL + t)) * rs + d0 + lane];
        sxz[r][lane] = v;
    }
    for (int r = ty; r < 32; r += 8) {
        int t = t0 + r;
        float v = xzres[((size_t)(b * LL + t)) * rs + DI + d0 + lane];
        sres[r][lane] = v / (1.f + __expf(-v));
    }
    __syncthreads();

    float wv[KC];
#pragma unroll
    for (int i = 0; i < KC; i++) wv[i] = w[(d0 + lane) * KC + i];
    const float bias = cb[d0 + lane];

    for (int r = ty; r < 32; r += 8) {
        float acc = bias;
#pragma unroll
        for (int i = 0; i < KC; i++)
            acc = fmaf(sxz[r + i][lane], wv[i], acc);
        float s = acc / (1.f + __expf(-acc));
        sout[r][lane] = s;
        xc[((size_t)(b * LL + t0 + r)) * DI + d0 + lane] = s;
    }
    __syncthreads();

    for (int r = ty; r < 32; r += 8) {
        xcT  [((size_t)(d0 + r)) * MM + b * LL + t0 + lane] = sout[lane][r];
        sresT[((size_t)(d0 + r)) * MM + b * LL + t0 + lane] = sres[lane][r];
    }
}

// ---------------------------------------------------------------------------
// Block-parallel selective scan, G=8 groups of 128 t (3 passes).
// ---------------------------------------------------------------------------
__global__ __launch_bounds__(256)
void scan_pass1(const float* __restrict__ deltaT,
                const float* __restrict__ xcT,
                const float* __restrict__ xdbl,
                const float* __restrict__ A_log,
                float* __restrict__ hend, float* __restrict__ sdlv)
{
    __shared__ float sB[GT][16];

    const int bx = blockIdx.x;
    const int dchunk = bx & 63;
    const int g = (bx >> 6) & (GG - 1);
    const int b = bx >> 9;
    const int n8 = threadIdx.x & 7;
    const int d = dchunk * 32 + (threadIdx.x >> 3);

    const float* xdB = xdbl + (size_t)b * LL * 96 + DTR;
    for (int i = threadIdx.x; i < GT * 16; i += 256) {
        int tt = i >> 4, c = i & 15;
        sB[tt][c] = xdB[(size_t)(g * GT + tt) * 96 + c];
    }
    __syncthreads();

    const float Adn0 = -expf(A_log[d * NS + n8]);
    const float Adn1 = -expf(A_log[d * NS + n8 + 8]);
    float h0 = 0.f, h1 = 0.f, sdl = 0.f;

    const size_t base = (size_t)d * MM + (size_t)b * LL + g * GT;
    const float4* dT4 = (const float4*)(deltaT + base);
    const float4* uT4 = (const float4*)(xcT + base);

    for (int tb = 0; tb < GT; tb += 4) {
        float4 dl4 = dT4[tb >> 2];
        float4 u4  = uT4[tb >> 2];
        float dls[4] = {dl4.x, dl4.y, dl4.z, dl4.w};
        float us[4]  = {u4.x,  u4.y,  u4.z,  u4.w};
#pragma unroll
        for (int j = 0; j < 4; j++) {
            const int tt = tb + j;
            float dl = dls[j];
            sdl += dl;
            float db = dl * us[j];
            h0 = fmaf(__expf(dl * Adn0), h0, db * sB[tt][n8]);
            h1 = fmaf(__expf(dl * Adn1), h1, db * sB[tt][n8 + 8]);
        }
    }
    const size_t o = (((size_t)b * DI + d) * GG + g) * NS;
    hend[o + n8] = h0;
    hend[o + n8 + 8] = h1;
    if (n8 == 0) sdlv[((size_t)b * DI + d) * GG + g] = sdl;
}

__global__ void scan_pass2(const float* __restrict__ hend,
                           const float* __restrict__ sdlv,
                           const float* __restrict__ A_log,
                           float* __restrict__ hcar)
{
    int tid = blockIdx.x * blockDim.x + threadIdx.x;
    int n = tid & 15;
    int d = (tid >> 4) & (DI - 1);
    int b = tid >> 15;
    const float Adn = -expf(A_log[d * NS + n]);
    float H = 0.f;
    const size_t ob = ((size_t)b * DI + d) * GG;
    for (int g = 0; g < GG; g++) {
        hcar[(ob + g) * NS + n] = H;
        H = fmaf(__expf(Adn * sdlv[ob + g]), H, hend[(ob + g) * NS + n]);
    }
}

__global__ __launch_bounds__(256)
void scan_pass3(const float* __restrict__ deltaT,
                const float* __restrict__ xcT,
                const float* __restrict__ sresT,
                const float* __restrict__ xdbl,
                const float* __restrict__ A_log,
                const float* __restrict__ Dp,
                const float* __restrict__ hcar,
                bf16* __restrict__ yh, bf16* __restrict__ yl)
{
    __shared__ float sBC[GT][32];

    const int bx = blockIdx.x;
    const int dchunk = bx & 63;
    const int g = (bx >> 6) & (GG - 1);
    const int b = bx >> 9;
    const int n8 = threadIdx.x & 7;
    const int d = dchunk * 32 + (threadIdx.x >> 3);

    const float* xdBC = xdbl + (size_t)b * LL * 96 + DTR;
    for (int i = threadIdx.x; i < GT * 32; i += 256) {
        int tt = i >> 5, c = i & 31;
        sBC[tt][c] = xdBC[(size_t)(g * GT + tt) * 96 + c];
    }
    __syncthreads();

    const float Adn0 = -expf(A_log[d * NS + n8]);
    const float Adn1 = -expf(A_log[d * NS + n8 + 8]);
    const float Dd = Dp[d];
    const size_t oc = (((size_t)b * DI + d) * GG + g) * NS;
    float h0 = hcar[oc + n8];
    float h1 = hcar[oc + n8 + 8];

    const size_t base = (size_t)d * MM + (size_t)b * LL + g * GT;
    const float4* dT4 = (const float4*)(deltaT + base);
    const float4* uT4 = (const float4*)(xcT + base);
    const float4* sT4 = (const float4*)(sresT + base);
    const size_t ybase = ((size_t)b * LL + g * GT) * DI + d;

    for (int tb = 0; tb < GT; tb += 4) {
        float4 dl4 = dT4[tb >> 2];
        float4 u4  = uT4[tb >> 2];
        float4 s4  = sT4[tb >> 2];
        float dls[4] = {dl4.x, dl4.y, dl4.z, dl4.w};
        float us[4]  = {u4.x,  u4.y,  u4.z,  u4.w};
        float ss[4]  = {s4.x,  s4.y,  s4.z,  s4.w};
        float yp[4];

#pragma unroll
        for (int j = 0; j < 4; j++) {
            const int tt = tb + j;
            float Bv0 = sBC[tt][n8];
            float Bv1 = sBC[tt][n8 + 8];
            float Cv0 = sBC[tt][n8 + 16];
            float Cv1 = sBC[tt][n8 + 24];
            float dl = dls[j];
            float e0 = __expf(dl * Adn0);
            float e1 = __expf(dl * Adn1);
            float db = dl * us[j];
            h0 = fmaf(e0, h0, db * Bv0);
            h1 = fmaf(e1, h1, db * Bv1);
            yp[j] = fmaf(h0, Cv0, h1 * Cv1);
        }

#pragma unroll
        for (int j = 0; j < 4; j++) yp[j] += __shfl_xor_sync(0xffffffffu, yp[j], 4);
#pragma unroll
        for (int j = 0; j < 4; j++) yp[j] += __shfl_xor_sync(0xffffffffu, yp[j], 2);
#pragma unroll
        for (int j = 0; j < 4; j++) yp[j] += __shfl_xor_sync(0xffffffffu, yp[j], 1);

        if (n8 == 0) {
#pragma unroll
            for (int j = 0; j < 4; j++) {
                float w = (yp[j] + us[j] * Dd) * ss[j];
                bf16 hb = __float2bfloat16(w);
                const size_t off = ybase + (size_t)(tb + j) * DI;
                yh[off] = hb;
                yl[off] = __float2bfloat16(w - __bfloat162float(hb));
            }
        }
    }
}

// ---------------------------------------------------------------------------
extern "C" void kernel_launch(void* const* d_in, const int* in_sizes, int n_in,
                              void* d_out, int out_size)
{
    const float* x      = (const float*)d_in[0];
    const float* W_in   = (const float*)d_in[1];
    const float* conv_w = (const float*)d_in[2];
    const float* conv_b = (const float*)d_in[3];
    const float* W_x    = (const float*)d_in[4];
    const float* W_dt   = (const float*)d_in[5];
    const float* b_dt   = (const float*)d_in[6];
    const float* A_log  = (const float*)d_in[7];
    const float* Dp     = (const float*)d_in[8];
    const float* W_out  = (const float*)d_in[9];
    float* out = (float*)d_out;

    float *p_xzres, *p_xc, *p_xcT, *p_sresT, *p_xdbl, *p_xpart, *p_opart, *p_deltaT;
    float *p_hend, *p_hcar, *p_sdl;
    bf16 *p_xh, *p_xl, *p_Winh, *p_Winl, *p_Wouth, *p_Woutl;
    bf16 *p_Wxh, *p_Wxl, *p_Wdth, *p_Wdtl, *p_xch, *p_xcl, *p_dth, *p_dtl, *p_yh, *p_yl;
    cudaGetSymbolAddress((void**)&p_xzres,  g_xzres);
    cudaGetSymbolAddress((void**)&p_xc,     g_xc);
    cudaGetSymbolAddress((void**)&p_xcT,    g_xcT);
    cudaGetSymbolAddress((void**)&p_sresT,  g_sresT);
    cudaGetSymbolAddress((void**)&p_xdbl,   g_xdbl);
    cudaGetSymbolAddress((void**)&p_xpart,  g_xpart);
    cudaGetSymbolAddress((void**)&p_opart,  g_opart);
    cudaGetSymbolAddress((void**)&p_deltaT, g_deltaT);
    cudaGetSymbolAddress((void**)&p_hend,   g_hend);
    cudaGetSymbolAddress((void**)&p_hcar,   g_hcar);
    cudaGetSymbolAddress((void**)&p_sdl,    g_sdl);
    cudaGetSymbolAddress((void**)&p_xh,     g_xh);
    cudaGetSymbolAddress((void**)&p_xl,     g_xl);
    cudaGetSymbolAddress((void**)&p_Winh,   g_Winh);
    cudaGetSymbolAddress((void**)&p_Winl,   g_Winl);
    cudaGetSymbolAddress((void**)&p_Wouth,  g_Wouth);
    cudaGetSymbolAddress((void**)&p_Woutl,  g_Woutl);
    cudaGetSymbolAddress((void**)&p_Wxh,    g_Wxh);
    cudaGetSymbolAddress((void**)&p_Wxl,    g_Wxl);
    cudaGetSymbolAddress((void**)&p_Wdth,   g_Wdth);
    cudaGetSymbolAddress((void**)&p_Wdtl,   g_Wdtl);
    cudaGetSymbolAddress((void**)&p_xch,    g_xch);
    cudaGetSymbolAddress((void**)&p_xcl,    g_xcl);
    cudaGetSymbolAddress((void**)&p_dth,    g_dth);
    cudaGetSymbolAddress((void**)&p_dtl,    g_dtl);
    cudaGetSymbolAddress((void**)&p_yh,     g_yh);
    cudaGetSymbolAddress((void**)&p_yl,     g_yl);

    cudaFuncSetAttribute(gemm_bf16x3<0, 1>,
                         cudaFuncAttributeMaxDynamicSharedMemorySize, 8 * TSB);
    cudaFuncSetAttribute(gemm_bf16x3<0, 2>,
                         cudaFuncAttributeMaxDynamicSharedMemorySize, 8 * TSB);
    cudaFuncSetAttribute(gemm_bf16x3<0, 8>,
                         cudaFuncAttributeMaxDynamicSharedMemorySize, 8 * TSB);
    cudaFuncSetAttribute(gemm_bf16x3<1, 1>,
                         cudaFuncAttributeMaxDynamicSharedMemorySize, 8 * TSB);

    // 0) fused bf16 hi/lo split of x, W_in, W_out, W_dt, W_x (one launch)
    split_all<<<(SEG4 + 255) / 256, 256>>>(
        x, W_in, W_out, W_dt, W_x,
        p_xh, p_xl, p_Winh, p_Winl, p_Wouth, p_Woutl,
        p_Wdth, p_Wdtl, p_Wxh, p_Wxl);

    // 1) in_proj (bf16x3): xzres[M,4096] = x @ W_in^T
    gemm_bf16x3<0, 1><<<dim3(2 * DI / BN3, MM / BM3), 256, 8 * TSB>>>(
        p_xh, p_xl, p_Winh, p_Winl, p_xzres, 2 * DI, DM, DM, 0, nullptr);

    // 2) causal conv + silu -> xc (fp32) + xcT + sresT  [validated R12 kernel]
    conv_silu_tr<<<dim3(DI / 32, LL / 32, BB), 256>>>(
        p_xzres, conv_w, conv_b, p_xc, p_xcT, p_sresT);

    // 2b) standalone bf16 split of xc for the x_proj tensor GEMM
    split_xc<<<(MM * DI / 4) / 256, 256>>>(p_xc, p_xch, p_xcl, MM * DI / 4);

    // 3) x_proj (bf16x3, split-K x8, padded N=128) + reduce (fused dt split)
    gemm_bf16x3<0, 8><<<dim3(1, MM / BM3, GG), 256, 8 * TSB>>>(
        p_xch, p_xcl, p_Wxh, p_Wxl, p_xpart, NXP, DI, DI / GG,
        (size_t)MM * NXP, nullptr);
    reduce_sk<<<(MM * 96) / 256, 256>>>(p_xpart, p_xdbl, p_dth, p_dtl, MM * 96);

    // 4) dt_proj (bf16x3, fused softplus + transposed store): deltaT[DI,M]
    gemm_bf16x3<1, 1><<<dim3(DI / BN3, MM / BM3), 256, 8 * TSB>>>(
        p_dth, p_dtl, p_Wdth, p_Wdtl, p_deltaT, 0, DTR, DTR, 0, b_dt);

    // 5) block-parallel selective scan (3 passes) -> y (bf16 hi/lo)
    scan_pass1<<<BB * GG * (DI / 32), 256>>>(
        p_deltaT, p_xcT, p_xdbl, A_log, p_hend, p_sdl);
    scan_pass2<<<(BB * DI * NS) / 256, 256>>>(p_hend, p_sdl, A_log, p_hcar);
    scan_pass3<<<BB * GG * (DI / 32), 256>>>(
        p_deltaT, p_xcT, p_sresT, p_xdbl, A_log, Dp, p_hcar, p_yh, p_yl);

    // 6) out_proj (bf16x3, split-K x2) + reduce -> out
    gemm_bf16x3<0, 2><<<dim3(DM / BN3, MM / BM3, 2), 256, 8 * TSB>>>(
        p_yh, p_yl, p_Wouth, p_Woutl, p_opart, DM, DI, DI / 2,
        (size_t)MM * DM, nullptr);
    reduce_out<<<(MM * DM / 4) / 256, 256>>>(p_opart, out, MM * DM / 4);
}

// round 15
// speedup vs baseline: 1.5273x; 1.0011x over previous
#include <cuda_runtime.h>
#include <cuda_bf16.h>
#include <cstdint>

// Problem dims
#define BB 2
#define LL 1024
#define DM 1024
#define DI 2048
#define NS 16
#define DTR 64
#define KC 4
#define MM (BB * LL)   // 2048 token rows
#define GG 8           // scan groups / split-K factor
#define GT (LL / GG)   // 128 t per group
#define NXP 128        // x_proj padded N (96 real + 32 zero)

typedef __nv_bfloat16 bf16;

// Scratch (static device buffers; allocation is forbidden)
__device__ float g_xzres[(size_t)BB * LL * 2 * DI];
__device__ float g_xc[(size_t)BB * LL * DI];          // conv+silu fp32 (row-major)
__device__ float g_xcT[(size_t)DI * MM];
__device__ float g_sresT[(size_t)DI * MM];
__device__ float g_xdbl[(size_t)BB * LL * 96];
__device__ float g_xpart[(size_t)GG * MM * NXP];
__device__ float g_opart[(size_t)2 * MM * DM];
__device__ float g_deltaT[(size_t)DI * MM];
__device__ float g_hend[(size_t)BB * DI * GG * NS];
__device__ float g_hcar[(size_t)BB * DI * GG * NS];
__device__ float g_sdl[(size_t)BB * DI * GG];
__device__ bf16 g_xh[(size_t)MM * DM],    g_xl[(size_t)MM * DM];
__device__ bf16 g_Winh[(size_t)2 * DI * DM], g_Winl[(size_t)2 * DI * DM];
__device__ bf16 g_Wouth[(size_t)DM * DI], g_Woutl[(size_t)DM * DI];
__device__ bf16 g_Wxh[(size_t)NXP * DI],  g_Wxl[(size_t)NXP * DI];   // rows 96..127 zero
__device__ bf16 g_Wdth[(size_t)DI * DTR], g_Wdtl[(size_t)DI * DTR];
__device__ bf16 g_xch[(size_t)MM * DI],   g_xcl[(size_t)MM * DI];
__device__ bf16 g_dth[(size_t)MM * DTR],  g_dtl[(size_t)MM * DTR];
__device__ bf16 g_yh[(size_t)MM * DI],    g_yl[(size_t)MM * DI];

__device__ __forceinline__ float softplusf(float v)
{
    return (v > 20.f) ? v : log1pf(expf(v));
}

// ===========================================================================
// Fused bf16 Dekker split of GEMM weight/input operands (one launch).
// ===========================================================================
#define SEG0 ((MM * DM) / 4)
#define SEG1 (SEG0 + (2 * DI * DM) / 4)
#define SEG2 (SEG1 + (DM * DI) / 4)
#define SEG3 (SEG2 + (DI * DTR) / 4)
#define SEG4 (SEG3 + (96 * DI) / 4)

__device__ __forceinline__ void split4(float4 v, uint2& h4, uint2& l4)
{
    bf16 h0 = __float2bfloat16(v.x), h1 = __float2bfloat16(v.y);
    bf16 h2 = __float2bfloat16(v.z), h3 = __float2bfloat16(v.w);
    bf16 l0 = __float2bfloat16(v.x - __bfloat162float(h0));
    bf16 l1 = __float2bfloat16(v.y - __bfloat162float(h1));
    bf16 l2 = __float2bfloat16(v.z - __bfloat162float(h2));
    bf16 l3 = __float2bfloat16(v.w - __bfloat162float(h3));
    __nv_bfloat162 hh0(h0, h1), hh1(h2, h3), ll0(l0, l1), ll1(l2, l3);
    h4.x = *(uint32_t*)&hh0; h4.y = *(uint32_t*)&hh1;
    l4.x = *(uint32_t*)&ll0; l4.y = *(uint32_t*)&ll1;
}

__global__ void split_all(const float* __restrict__ x,
                          const float* __restrict__ Wi,
                          const float* __restrict__ Wo,
                          const float* __restrict__ Wd,
                          const float* __restrict__ Wx,
                          bf16* __restrict__ xh, bf16* __restrict__ xl,
                          bf16* __restrict__ Wih, bf16* __restrict__ Wil,
                          bf16* __restrict__ Woh, bf16* __restrict__ Wol,
                          bf16* __restrict__ Wdh, bf16* __restrict__ Wdl,
                          bf16* __restrict__ Wxh, bf16* __restrict__ Wxl)
{
    int i = blockIdx.x * blockDim.x + threadIdx.x;   // float4 index
    if (i >= SEG4) return;
    const float4* src;
    uint2 *hi, *lo;
    int j;
    if (i < SEG0)      { j = i;        src = (const float4*)x;  hi = (uint2*)xh;  lo = (uint2*)xl; }
    else if (i < SEG1) { j = i - SEG0; src = (const float4*)Wi; hi = (uint2*)Wih; lo = (uint2*)Wil; }
    else if (i < SEG2) { j = i - SEG1; src = (const float4*)Wo; hi = (uint2*)Woh; lo = (uint2*)Wol; }
    else if (i < SEG3) { j = i - SEG2; src = (const float4*)Wd; hi = (uint2*)Wdh; lo = (uint2*)Wdl; }
    else               { j = i - SEG3; src = (const float4*)Wx; hi = (uint2*)Wxh; lo = (uint2*)Wxl; }
    uint2 h4, l4;
    split4(src[j], h4, l4);
    hi[j] = h4;
    lo[j] = l4;
}

// Standalone bf16 split of xc.
__global__ void split_xc(const float* __restrict__ src,
                         bf16* __restrict__ hi, bf16* __restrict__ lo, int n4)
{
    int i = blockIdx.x * blockDim.x + threadIdx.x;
    if (i >= n4) return;
    uint2 h4, l4;
    split4(((const float4*)src)[i], h4, l4);
    ((uint2*)hi)[i] = h4;
    ((uint2*)lo)[i] = l4;
}

#define CP16(dst_u32, src_ptr) \
    asm volatile("cp.async.cg.shared.global [%0], [%1], 16;" :: "r"(dst_u32), "l"(src_ptr))

__device__ __forceinline__ void mma_bf16(float* d, const uint32_t* a, const uint32_t* b)
{
    asm volatile(
        "mma.sync.aligned.m16n8k16.row.col.f32.bf16.bf16.f32 "
        "{%0,%1,%2,%3}, {%4,%5,%6,%7}, {%8,%9}, {%0,%1,%2,%3};"
        : "+f"(d[0]), "+f"(d[1]), "+f"(d[2]), "+f"(d[3])
        : "r"(a[0]), "r"(a[1]), "r"(a[2]), "r"(a[3]), "r"(b[0]), "r"(b[1]));
}

__device__ __forceinline__ void ldsm4(uint32_t& r0, uint32_t& r1,
                                      uint32_t& r2, uint32_t& r3, uint32_t addr)
{
    asm volatile("ldmatrix.sync.aligned.m8n8.x4.shared.b16 {%0,%1,%2,%3}, [%4];"
                 : "=r"(r0), "=r"(r1), "=r"(r2), "=r"(r3) : "r"(addr));
}

// ===========================================================================
// mma.sync bf16x3 GEMM: C[M,N] = A[M,K] @ B[N,K]^T, fp32 out.
// 128x128 tile, 8 warps of 64x32, BK=32, 2-stage cp.async, ldmatrix,
// 2 CTAs/SM. Term-major MMA sweeps (independent accumulators back-to-back).
// MODE 0: plain store. MODE 1: softplus(acc+bias) transposed.
// SPLITK>1: blockIdx.z K-slice, C += z*zstride.
// ===========================================================================
#define BM3 128
#define BN3 128
#define BK3 32
#define ROWB 80
#define TSB (128 * ROWB)

template <int MODE, int SPLITK>
__global__ __launch_bounds__(256, 2)
void gemm_bf16x3(const bf16* __restrict__ Ahg, const bf16* __restrict__ Alg,
                 const bf16* __restrict__ Bhg, const bf16* __restrict__ Blg,
                 float* __restrict__ C, int ldc, int ldk, int kcount,
                 size_t zstride, const float* __restrict__ bias)
{
    extern __shared__ char sm[];
    const uint32_t sbase = (uint32_t)__cvta_generic_to_shared(sm);
    const uint32_t oAh = 0, oAl = 2 * TSB, oBh = 4 * TSB, oBl = 6 * TSB;

    const int tid  = threadIdx.x;
    const int warp = tid >> 5, lane = tid & 31;
    const int wm = (warp & 1) * 64;
    const int wn = (warp >> 1) * 32;
    const int g  = lane >> 2;
    const int tg = lane & 3;
    const int row0 = blockIdx.y * BM3;
    const int col0 = blockIdx.x * BN3;
    const int kbeg = (SPLITK > 1) ? blockIdx.z * kcount : 0;
    if (SPLITK > 1) C += (size_t)blockIdx.z * zstride;

    const int lrow = tid >> 1;
    const int lcb  = (tid & 1) * 16;

    const int lrA  = lane & 15;
    const int lkA  = (lane >> 4) * 16;
    const int lrB  = (lane & 7) + ((lane >> 4) << 3);
    const int lkB  = ((lane >> 3) & 1) * 16;

    float acc[4][4][4] = {};
    const int iters = kcount / BK3;

    auto load_tile = [&](int tile) {
        const int s = tile & 1;
        const int k0 = kbeg + tile * BK3;
        {
            const bf16* p = Ahg + (size_t)(row0 + lrow) * ldk + k0 + lcb;
            uint32_t d = sbase + oAh + s * TSB + lrow * ROWB + lcb * 2;
            CP16(d, p); CP16(d + 16, p + 8);
        }
        {
            const bf16* p = Alg + (size_t)(row0 + lrow) * ldk + k0 + lcb;
            uint32_t d = sbase + oAl + s * TSB + lrow * ROWB + lcb * 2;
            CP16(d, p); CP16(d + 16, p + 8);
        }
        {
            const bf16* p = Bhg + (size_t)(col0 + lrow) * ldk + k0 + lcb;
            uint32_t d = sbase + oBh + s * TSB + lrow * ROWB + lcb * 2;
            CP16(d, p); CP16(d + 16, p + 8);
        }
        {
            const bf16* p = Blg + (size_t)(col0 + lrow) * ldk + k0 + lcb;
            uint32_t d = sbase + oBl + s * TSB + lrow * ROWB + lcb * 2;
            CP16(d, p); CP16(d + 16, p + 8);
        }
        asm volatile("cp.async.commit_group;");
    };

    load_tile(0);

    for (int it = 0; it < iters; ++it) {
        if (it + 1 < iters) {
            load_tile(it + 1);
            asm volatile("cp.async.wait_group 1;");
        } else {
            asm volatile("cp.async.wait_group 0;");
        }
        __syncthreads();

        const int s = it & 1;
        const uint32_t bAh = sbase + oAh + s * TSB;
        const uint32_t bAl = sbase + oAl + s * TSB;
        const uint32_t bBh = sbase + oBh + s * TSB;
        const uint32_t bBl = sbase + oBl + s * TSB;

#pragma unroll
        for (int ks = 0; ks < 2; ++ks) {
            const int kb = ks * 32;
            uint32_t ah[4][4], al[4][4], bh[4][2], bl[4][2];
#pragma unroll
            for (int mt = 0; mt < 4; ++mt) {
                const uint32_t ra = (wm + mt * 16 + lrA) * ROWB + kb + lkA;
                ldsm4(ah[mt][0], ah[mt][1], ah[mt][2], ah[mt][3], bAh + ra);
                ldsm4(al[mt][0], al[mt][1], al[mt][2], al[mt][3], bAl + ra);
            }
#pragma unroll
            for (int np = 0; np < 2; ++np) {
                const uint32_t rb = (wn + np * 16 + lrB) * ROWB + kb + lkB;
                ldsm4(bh[2*np][0], bh[2*np][1], bh[2*np+1][0], bh[2*np+1][1], bBh + rb);
                ldsm4(bl[2*np][0], bl[2*np][1], bl[2*np+1][0], bl[2*np+1][1], bBl + rb);
            }
            // Term-major sweeps: adjacent MMAs use distinct accumulators,
            // per-acc accumulation order unchanged (albh -> ahbl -> ahbh).
#pragma unroll
            for (int mt = 0; mt < 4; ++mt)
#pragma unroll
                for (int nt = 0; nt < 4; ++nt)
                    mma_bf16(acc[mt][nt], al[mt], bh[nt]);
#pragma unroll
            for (int mt = 0; mt < 4; ++mt)
#pragma unroll
                for (int nt = 0; nt < 4; ++nt)
                    mma_bf16(acc[mt][nt], ah[mt], bl[nt]);
#pragma unroll
            for (int mt = 0; mt < 4; ++mt)
#pragma unroll
                for (int nt = 0; nt < 4; ++nt)
                    mma_bf16(acc[mt][nt], ah[mt], bh[nt]);
        }
        __syncthreads();
    }

    if (MODE == 0) {
#pragma unroll
        for (int mt = 0; mt < 4; ++mt) {
#pragma unroll
            for (int nt = 0; nt < 4; ++nt) {
                const int gr = row0 + wm + mt * 16 + g;
                const int gc = col0 + wn + nt * 8 + tg * 2;
                *(float2*)&C[(size_t)gr * ldc + gc] =
                    make_float2(acc[mt][nt][0], acc[mt][nt][1]);
                *(float2*)&C[(size_t)(gr + 8) * ldc + gc] =
                    make_float2(acc[mt][nt][2], acc[mt][nt][3]);
            }
        }
    } else {
        // softplus(acc + bias[col]) -> smem tile -> transposed coalesced store
        float (*st)[133] = (float(*)[133])sm;
#pragma unroll
        for (int mt = 0; mt < 4; ++mt) {
#pragma unroll
            for (int nt = 0; nt < 4; ++nt) {
                const int lr = wm + mt * 16 + g;
                const int lc = wn + nt * 8 + tg * 2;
                const float b0 = bias[col0 + lc];
                const float b1 = bias[col0 + lc + 1];
                st[lr][lc]          = softplusf(acc[mt][nt][0] + b0);
                st[lr][lc + 1]      = softplusf(acc[mt][nt][1] + b1);
                st[lr + 8][lc]      = softplusf(acc[mt][nt][2] + b0);
                st[lr + 8][lc + 1]  = softplusf(acc[mt][nt][3] + b1);
            }
        }
        __syncthreads();
#pragma unroll
        for (int ci = 0; ci < 16; ++ci) {
            const int c = warp + ci * 8;
            float* dst = C + (size_t)(col0 + c) * MM + row0;
#pragma unroll
            for (int k = 0; k < 4; ++k)
                dst[32 * k + lane] = st[32 * k + lane][c];
        }
    }
}

// ---------------------------------------------------------------------------
// out_proj split-K reduce (float4): out = part0 + part1
// ---------------------------------------------------------------------------
__global__ void reduce_out(const float* __restrict__ part,
                           float* __restrict__ out, int n4)
{
    int i = blockIdx.x * blockDim.x + threadIdx.x;
    if (i >= n4) return;
    const float4* p0 = (const float4*)part;
    const float4* p1 = p0 + n4;
    float4 a = p0[i], b = p1[i];
    ((float4*)out)[i] = make_float4(a.x + b.x, a.y + b.y, a.z + b.z, a.w + b.w);
}

// x_proj reduce over [z][M][NXP] partials -> xdbl[M,96];
// also emits bf16 hi/lo split of the first 64 cols (dt input).
__global__ void reduce_sk(const float* __restrict__ part,
                          float* __restrict__ out,
                          bf16* __restrict__ dth, bf16* __restrict__ dtl, int n)
{
    int i = blockIdx.x * blockDim.x + threadIdx.x;
    if (i >= n) return;
    int row = i / 96;
    int col = i % 96;
    float s = 0.f;
#pragma unroll
    for (int z = 0; z < GG; z++)
        s += part[(size_t)z * MM * NXP + (size_t)row * NXP + col];
    out[i] = s;
    if (col < DTR) {
        bf16 h = __float2bfloat16(s);
        dth[(size_t)row * DTR + col] = h;
        dtl[(size_t)row * DTR + col] = __float2bfloat16(s - __bfloat162float(h));
    }
}

// ---------------------------------------------------------------------------
// Causal depthwise conv1d (k=4) + SiLU, tiled (validated R12 version).
// Emits xc (fp32 row-major), xc_T, silu(res)_T.
// ---------------------------------------------------------------------------
__global__ __launch_bounds__(256)
void conv_silu_tr(const float* __restrict__ xzres,
                  const float* __restrict__ w,
                  const float* __restrict__ cb,
                  float* __restrict__ xc,
                  float* __restrict__ xcT,
                  float* __restrict__ sresT)
{
    __shared__ float sxz[36][33];
    __shared__ float sout[32][33];
    __shared__ float sres[32][33];

    const int d0 = blockIdx.x * 32;
    const int t0 = blockIdx.y * 32;
    const int b  = blockIdx.z;
    const int lane = threadIdx.x & 31;
    const int ty   = threadIdx.x >> 5;
    const size_t rs = 2 * DI;

    for (int r = ty; r < 35; r += 8) {
        int t = t0 - 3 + r;
        float v = 0.f;
        if (t >= 0) v = xzres[((size_t)(b * LL + t)) * rs + d0 + lane];
        sxz[r][lane] = v;
    }
    for (int r = ty; r < 32; r += 8) {
        int t = t0 + r;
        float v = xzres[((size_t)(b * LL + t)) * rs + DI + d0 + lane];
        sres[r][lane] = v / (1.f + __expf(-v));
    }
    __syncthreads();

    float wv[KC];
#pragma unroll
    for (int i = 0; i < KC; i++) wv[i] = w[(d0 + lane) * KC + i];
    const float bias = cb[d0 + lane];

    for (int r = ty; r < 32; r += 8) {
        float acc = bias;
#pragma unroll
        for (int i = 0; i < KC; i++)
            acc = fmaf(sxz[r + i][lane], wv[i], acc);
        float s = acc / (1.f + __expf(-acc));
        sout[r][lane] = s;
        xc[((size_t)(b * LL + t0 + r)) * DI + d0 + lane] = s;
    }
    __syncthreads();

    for (int r = ty; r < 32; r += 8) {
        xcT  [((size_t)(d0 + r)) * MM + b * LL + t0 + lane] = sout[lane][r];
        sresT[((size_t)(d0 + r)) * MM + b * LL + t0 + lane] = sres[lane][r];
    }
}

// ---------------------------------------------------------------------------
// Block-parallel selective scan, G=8 groups of 128 t (3 passes).
// ---------------------------------------------------------------------------
__global__ __launch_bounds__(256)
void scan_pass1(const float* __restrict__ deltaT,
                const float* __restrict__ xcT,
                const float* __restrict__ xdbl,
                const float* __restrict__ A_log,
                float* __restrict__ hend, float* __restrict__ sdlv)
{
    __shared__ float sB[GT][16];

    const int bx = blockIdx.x;
    const int dchunk = bx & 63;
    const int g = (bx >> 6) & (GG - 1);
    const int b = bx >> 9;
    const int n8 = threadIdx.x & 7;
    const int d = dchunk * 32 + (threadIdx.x >> 3);

    const float* xdB = xdbl + (size_t)b * LL * 96 + DTR;
    for (int i = threadIdx.x; i < GT * 16; i += 256) {
        int tt = i >> 4, c = i & 15;
        sB[tt][c] = xdB[(size_t)(g * GT + tt) * 96 + c];
    }
    __syncthreads();

    const float Adn0 = -expf(A_log[d * NS + n8]);
    const float Adn1 = -expf(A_log[d * NS + n8 + 8]);
    float h0 = 0.f, h1 = 0.f, sdl = 0.f;

    const size_t base = (size_t)d * MM + (size_t)b * LL + g * GT;
    const float4* dT4 = (const float4*)(deltaT + base);
    const float4* uT4 = (const float4*)(xcT + base);

    for (int tb = 0; tb < GT; tb += 4) {
        float4 dl4 = dT4[tb >> 2];
        float4 u4  = uT4[tb >> 2];
        float dls[4] = {dl4.x, dl4.y, dl4.z, dl4.w};
        float us[4]  = {u4.x,  u4.y,  u4.z,  u4.w};
#pragma unroll
        for (int j = 0; j < 4; j++) {
            const int tt = tb + j;
            float dl = dls[j];
            sdl += dl;
            float db = dl * us[j];
            h0 = fmaf(__expf(dl * Adn0), h0, db * sB[tt][n8]);
            h1 = fmaf(__expf(dl * Adn1), h1, db * sB[tt][n8 + 8]);
        }
    }
    const size_t o = (((size_t)b * DI + d) * GG + g) * NS;
    hend[o + n8] = h0;
    hend[o + n8 + 8] = h1;
    if (n8 == 0) sdlv[((size_t)b * DI + d) * GG + g] = sdl;
}

__global__ void scan_pass2(const float* __restrict__ hend,
                           const float* __restrict__ sdlv,
                           const float* __restrict__ A_log,
                           float* __restrict__ hcar)
{
    int tid = blockIdx.x * blockDim.x + threadIdx.x;
    int n = tid & 15;
    int d = (tid >> 4) & (DI - 1);
    int b = tid >> 15;
    const float Adn = -expf(A_log[d * NS + n]);
    float H = 0.f;
    const size_t ob = ((size_t)b * DI + d) * GG;
    for (int g = 0; g < GG; g++) {
        hcar[(ob + g) * NS + n] = H;
        H = fmaf(__expf(Adn * sdlv[ob + g]), H, hend[(ob + g) * NS + n]);
    }
}

__global__ __launch_bounds__(256)
void scan_pass3(const float* __restrict__ deltaT,
                const float* __restrict__ xcT,
                const float* __restrict__ sresT,
                const float* __restrict__ xdbl,
                const float* __restrict__ A_log,
                const float* __restrict__ Dp,
                const float* __restrict__ hcar,
                bf16* __restrict__ yh, bf16* __restrict__ yl)
{
    __shared__ float sBC[GT][32];

    const int bx = blockIdx.x;
    const int dchunk = bx & 63;
    const int g = (bx >> 6) & (GG - 1);
    const int b = bx >> 9;
    const int n8 = threadIdx.x & 7;
    const int d = dchunk * 32 + (threadIdx.x >> 3);

    const float* xdBC = xdbl + (size_t)b * LL * 96 + DTR;
    for (int i = threadIdx.x; i < GT * 32; i += 256) {
        int tt = i >> 5, c = i & 31;
        sBC[tt][c] = xdBC[(size_t)(g * GT + tt) * 96 + c];
    }
    __syncthreads();

    const float Adn0 = -expf(A_log[d * NS + n8]);
    const float Adn1 = -expf(A_log[d * NS + n8 + 8]);
    const float Dd = Dp[d];
    const size_t oc = (((size_t)b * DI + d) * GG + g) * NS;
    float h0 = hcar[oc + n8];
    float h1 = hcar[oc + n8 + 8];

    const size_t base = (size_t)d * MM + (size_t)b * LL + g * GT;
    const float4* dT4 = (const float4*)(deltaT + base);
    const float4* uT4 = (const float4*)(xcT + base);
    const float4* sT4 = (const float4*)(sresT + base);
    const size_t ybase = ((size_t)b * LL + g * GT) * DI + d;

    for (int tb = 0; tb < GT; tb += 4) {
        float4 dl4 = dT4[tb >> 2];
        float4 u4  = uT4[tb >> 2];
        float4 s4  = sT4[tb >> 2];
        float dls[4] = {dl4.x, dl4.y, dl4.z, dl4.w};
        float us[4]  = {u4.x,  u4.y,  u4.z,  u4.w};
        float ss[4]  = {s4.x,  s4.y,  s4.z,  s4.w};
        float yp[4];

#pragma unroll
        for (int j = 0; j < 4; j++) {
            const int tt = tb + j;
            float Bv0 = sBC[tt][n8];
            float Bv1 = sBC[tt][n8 + 8];
            float Cv0 = sBC[tt][n8 + 16];
            float Cv1 = sBC[tt][n8 + 24];
            float dl = dls[j];
            float e0 = __expf(dl * Adn0);
            float e1 = __expf(dl * Adn1);
            float db = dl * us[j];
            h0 = fmaf(e0, h0, db * Bv0);
            h1 = fmaf(e1, h1, db * Bv1);
            yp[j] = fmaf(h0, Cv0, h1 * Cv1);
        }

#pragma unroll
        for (int j = 0; j < 4; j++) yp[j] += __shfl_xor_sync(0xffffffffu, yp[j], 4);
#pragma unroll
        for (int j = 0; j < 4; j++) yp[j] += __shfl_xor_sync(0xffffffffu, yp[j], 2);
#pragma unroll
        for (int j = 0; j < 4; j++) yp[j] += __shfl_xor_sync(0xffffffffu, yp[j], 1);

        if (n8 == 0) {
#pragma unroll
            for (int j = 0; j < 4; j++) {
                float w = (yp[j] + us[j] * Dd) * ss[j];
                bf16 hb = __float2bfloat16(w);
                const size_t off = ybase + (size_t)(tb + j) * DI;
                yh[off] = hb;
                yl[off] = __float2bfloat16(w - __bfloat162float(hb));
            }
        }
    }
}

// ---------------------------------------------------------------------------
extern "C" void kernel_launch(void* const* d_in, const int* in_sizes, int n_in,
                              void* d_out, int out_size)
{
    const float* x      = (const float*)d_in[0];
    const float* W_in   = (const float*)d_in[1];
    const float* conv_w = (const float*)d_in[2];
    const float* conv_b = (const float*)d_in[3];
    const float* W_x    = (const float*)d_in[4];
    const float* W_dt   = (const float*)d_in[5];
    const float* b_dt   = (const float*)d_in[6];
    const float* A_log  = (const float*)d_in[7];
    const float* Dp     = (const float*)d_in[8];
    const float* W_out  = (const float*)d_in[9];
    float* out = (float*)d_out;

    float *p_xzres, *p_xc, *p_xcT, *p_sresT, *p_xdbl, *p_xpart, *p_opart, *p_deltaT;
    float *p_hend, *p_hcar, *p_sdl;
    bf16 *p_xh, *p_xl, *p_Winh, *p_Winl, *p_Wouth, *p_Woutl;
    bf16 *p_Wxh, *p_Wxl, *p_Wdth, *p_Wdtl, *p_xch, *p_xcl, *p_dth, *p_dtl, *p_yh, *p_yl;
    cudaGetSymbolAddress((void**)&p_xzres,  g_xzres);
    cudaGetSymbolAddress((void**)&p_xc,     g_xc);
    cudaGetSymbolAddress((void**)&p_xcT,    g_xcT);
    cudaGetSymbolAddress((void**)&p_sresT,  g_sresT);
    cudaGetSymbolAddress((void**)&p_xdbl,   g_xdbl);
    cudaGetSymbolAddress((void**)&p_xpart,  g_xpart);
    cudaGetSymbolAddress((void**)&p_opart,  g_opart);
    cudaGetSymbolAddress((void**)&p_deltaT, g_deltaT);
    cudaGetSymbolAddress((void**)&p_hend,   g_hend);
    cudaGetSymbolAddress((void**)&p_hcar,   g_hcar);
    cudaGetSymbolAddress((void**)&p_sdl,    g_sdl);
    cudaGetSymbolAddress((void**)&p_xh,     g_xh);
    cudaGetSymbolAddress((void**)&p_xl,     g_xl);
    cudaGetSymbolAddress((void**)&p_Winh,   g_Winh);
    cudaGetSymbolAddress((void**)&p_Winl,   g_Winl);
    cudaGetSymbolAddress((void**)&p_Wouth,  g_Wouth);
    cudaGetSymbolAddress((void**)&p_Woutl,  g_Woutl);
    cudaGetSymbolAddress((void**)&p_Wxh,    g_Wxh);
    cudaGetSymbolAddress((void**)&p_Wxl,    g_Wxl);
    cudaGetSymbolAddress((void**)&p_Wdth,   g_Wdth);
    cudaGetSymbolAddress((void**)&p_Wdtl,   g_Wdtl);
    cudaGetSymbolAddress((void**)&p_xch,    g_xch);
    cudaGetSymbolAddress((void**)&p_xcl,    g_xcl);
    cudaGetSymbolAddress((void**)&p_dth,    g_dth);
    cudaGetSymbolAddress((void**)&p_dtl,    g_dtl);
    cudaGetSymbolAddress((void**)&p_yh,     g_yh);
    cudaGetSymbolAddress((void**)&p_yl,     g_yl);

    cudaFuncSetAttribute(gemm_bf16x3<0, 1>,
                         cudaFuncAttributeMaxDynamicSharedMemorySize, 8 * TSB);
    cudaFuncSetAttribute(gemm_bf16x3<0, 2>,
                         cudaFuncAttributeMaxDynamicSharedMemorySize, 8 * TSB);
    cudaFuncSetAttribute(gemm_bf16x3<0, 8>,
                         cudaFuncAttributeMaxDynamicSharedMemorySize, 8 * TSB);
    cudaFuncSetAttribute(gemm_bf16x3<1, 1>,
                         cudaFuncAttributeMaxDynamicSharedMemorySize, 8 * TSB);

    // 0) fused bf16 hi/lo split of x, W_in, W_out, W_dt, W_x (one launch)
    split_all<<<(SEG4 + 255) / 256, 256>>>(
        x, W_in, W_out, W_dt, W_x,
        p_xh, p_xl, p_Winh, p_Winl, p_Wouth, p_Woutl,
        p_Wdth, p_Wdtl, p_Wxh, p_Wxl);

    // 1) in_proj (bf16x3): xzres[M,4096] = x @ W_in^T
    gemm_bf16x3<0, 1><<<dim3(2 * DI / BN3, MM / BM3), 256, 8 * TSB>>>(
        p_xh, p_xl, p_Winh, p_Winl, p_xzres, 2 * DI, DM, DM, 0, nullptr);

    // 2) causal conv + silu -> xc (fp32) + xcT + sresT  [validated R12 kernel]
    conv_silu_tr<<<dim3(DI / 32, LL / 32, BB), 256>>>(
        p_xzres, conv_w, conv_b, p_xc, p_xcT, p_sresT);

    // 2b) standalone bf16 split of xc for the x_proj tensor GEMM
    split_xc<<<(MM * DI / 4) / 256, 256>>>(p_xc, p_xch, p_xcl, MM * DI / 4);

    // 3) x_proj (bf16x3, split-K x8, padded N=128) + reduce (fused dt split)
    gemm_bf16x3<0, 8><<<dim3(1, MM / BM3, GG), 256, 8 * TSB>>>(
        p_xch, p_xcl, p_Wxh, p_Wxl, p_xpart, NXP, DI, DI / GG,
        (size_t)MM * NXP, nullptr);
    reduce_sk<<<(MM * 96) / 256, 256>>>(p_xpart, p_xdbl, p_dth, p_dtl, MM * 96);

    // 4) dt_proj (bf16x3, fused softplus + transposed store): deltaT[DI,M]
    gemm_bf16x3<1, 1><<<dim3(DI / BN3, MM / BM3), 256, 8 * TSB>>>(
        p_dth, p_dtl, p_Wdth, p_Wdtl, p_deltaT, 0, DTR, DTR, 0, b_dt);

    // 5) block-parallel selective scan (3 passes) -> y (bf16 hi/lo)
    scan_pass1<<<BB * GG * (DI / 32), 256>>>(
        p_deltaT, p_xcT, p_xdbl, A_log, p_hend, p_sdl);
    scan_pass2<<<(BB * DI * NS) / 256, 256>>>(p_hend, p_sdl, A_log, p_hcar);
    scan_pass3<<<BB * GG * (DI / 32), 256>>>(
        p_deltaT, p_xcT, p_sresT, p_xdbl, A_log, Dp, p_hcar, p_yh, p_yl);

    // 6) out_proj (bf16x3, split-K x2) + reduce -> out
    gemm_bf16x3<0, 2><<<dim3(DM / BN3, MM / BM3, 2), 256, 8 * TSB>>>(
        p_yh, p_yl, p_Wouth, p_Woutl, p_opart, DM, DI, DI / 2,
        (size_t)MM * DM, nullptr);
    reduce_out<<<(MM * DM / 4) / 256, 256>>>(p_opart, out, MM * DM / 4);
}

// round 16
// speedup vs baseline: 1.5338x; 1.0042x over previous
#include <cuda_runtime.h>
#include <cuda_bf16.h>
#include <cstdint>

// Problem dims
#define BB 2
#define LL 1024
#define DM 1024
#define DI 2048
#define NS 16
#define DTR 64
#define KC 4
#define MM (BB * LL)   // 2048 token rows
#define GG 8           // scan groups / split-K factor
#define GT (LL / GG)   // 128 t per group
#define NXP 128        // x_proj padded N (96 real + 32 zero)

typedef __nv_bfloat16 bf16;

// Scratch (static device buffers; allocation is forbidden)
__device__ float g_xzres[(size_t)BB * LL * 2 * DI];
__device__ float g_xc[(size_t)BB * LL * DI];          // conv+silu fp32 (row-major)
__device__ float g_xcT[(size_t)DI * MM];
__device__ float g_sresT[(size_t)DI * MM];
__device__ float g_xdbl[(size_t)BB * LL * 96];
__device__ float g_xpart[(size_t)GG * MM * NXP];
__device__ float g_opart[(size_t)2 * MM * DM];
__device__ float g_deltaT[(size_t)DI * MM];
__device__ float g_hend[(size_t)BB * DI * GG * NS];
__device__ float g_hcar[(size_t)BB * DI * GG * NS];
__device__ float g_sdl[(size_t)BB * DI * GG];
__device__ bf16 g_xh[(size_t)MM * DM],    g_xl[(size_t)MM * DM];
__device__ bf16 g_Winh[(size_t)2 * DI * DM], g_Winl[(size_t)2 * DI * DM];
__device__ bf16 g_Wouth[(size_t)DM * DI], g_Woutl[(size_t)DM * DI];
__device__ bf16 g_Wxh[(size_t)NXP * DI],  g_Wxl[(size_t)NXP * DI];   // rows 96..127 zero
__device__ bf16 g_Wdth[(size_t)DI * DTR], g_Wdtl[(size_t)DI * DTR];
__device__ bf16 g_xch[(size_t)MM * DI],   g_xcl[(size_t)MM * DI];
__device__ bf16 g_dth[(size_t)MM * DTR],  g_dtl[(size_t)MM * DTR];
__device__ bf16 g_yh[(size_t)MM * DI],    g_yl[(size_t)MM * DI];

__device__ __forceinline__ float softplusf(float v)
{
    return (v > 20.f) ? v : log1pf(expf(v));
}

// ===========================================================================
// Fused bf16 Dekker split of GEMM weight/input operands (one launch).
// ===========================================================================
#define SEG0 ((MM * DM) / 4)
#define SEG1 (SEG0 + (2 * DI * DM) / 4)
#define SEG2 (SEG1 + (DM * DI) / 4)
#define SEG3 (SEG2 + (DI * DTR) / 4)
#define SEG4 (SEG3 + (96 * DI) / 4)

__device__ __forceinline__ void split4(float4 v, uint2& h4, uint2& l4)
{
    bf16 h0 = __float2bfloat16(v.x), h1 = __float2bfloat16(v.y);
    bf16 h2 = __float2bfloat16(v.z), h3 = __float2bfloat16(v.w);
    bf16 l0 = __float2bfloat16(v.x - __bfloat162float(h0));
    bf16 l1 = __float2bfloat16(v.y - __bfloat162float(h1));
    bf16 l2 = __float2bfloat16(v.z - __bfloat162float(h2));
    bf16 l3 = __float2bfloat16(v.w - __bfloat162float(h3));
    __nv_bfloat162 hh0(h0, h1), hh1(h2, h3), ll0(l0, l1), ll1(l2, l3);
    h4.x = *(uint32_t*)&hh0; h4.y = *(uint32_t*)&hh1;
    l4.x = *(uint32_t*)&ll0; l4.y = *(uint32_t*)&ll1;
}

__global__ void split_all(const float* __restrict__ x,
                          const float* __restrict__ Wi,
                          const float* __restrict__ Wo,
                          const float* __restrict__ Wd,
                          const float* __restrict__ Wx,
                          bf16* __restrict__ xh, bf16* __restrict__ xl,
                          bf16* __restrict__ Wih, bf16* __restrict__ Wil,
                          bf16* __restrict__ Woh, bf16* __restrict__ Wol,
                          bf16* __restrict__ Wdh, bf16* __restrict__ Wdl,
                          bf16* __restrict__ Wxh, bf16* __restrict__ Wxl)
{
    int i = blockIdx.x * blockDim.x + threadIdx.x;   // float4 index
    if (i >= SEG4) return;
    const float4* src;
    uint2 *hi, *lo;
    int j;
    if (i < SEG0)      { j = i;        src = (const float4*)x;  hi = (uint2*)xh;  lo = (uint2*)xl; }
    else if (i < SEG1) { j = i - SEG0; src = (const float4*)Wi; hi = (uint2*)Wih; lo = (uint2*)Wil; }
    else if (i < SEG2) { j = i - SEG1; src = (const float4*)Wo; hi = (uint2*)Woh; lo = (uint2*)Wol; }
    else if (i < SEG3) { j = i - SEG2; src = (const float4*)Wd; hi = (uint2*)Wdh; lo = (uint2*)Wdl; }
    else               { j = i - SEG3; src = (const float4*)Wx; hi = (uint2*)Wxh; lo = (uint2*)Wxl; }
    uint2 h4, l4;
    split4(src[j], h4, l4);
    hi[j] = h4;
    lo[j] = l4;
}

// Standalone bf16 split of xc.
__global__ void split_xc(const float* __restrict__ src,
                         bf16* __restrict__ hi, bf16* __restrict__ lo, int n4)
{
    int i = blockIdx.x * blockDim.x + threadIdx.x;
    if (i >= n4) return;
    uint2 h4, l4;
    split4(((const float4*)src)[i], h4, l4);
    ((uint2*)hi)[i] = h4;
    ((uint2*)lo)[i] = l4;
}

#define CP16(dst_u32, src_ptr) \
    asm volatile("cp.async.cg.shared.global [%0], [%1], 16;" :: "r"(dst_u32), "l"(src_ptr))

__device__ __forceinline__ void mma_bf16(float* d, const uint32_t* a, const uint32_t* b)
{
    asm volatile(
        "mma.sync.aligned.m16n8k16.row.col.f32.bf16.bf16.f32 "
        "{%0,%1,%2,%3}, {%4,%5,%6,%7}, {%8,%9}, {%0,%1,%2,%3};"
        : "+f"(d[0]), "+f"(d[1]), "+f"(d[2]), "+f"(d[3])
        : "r"(a[0]), "r"(a[1]), "r"(a[2]), "r"(a[3]), "r"(b[0]), "r"(b[1]));
}

__device__ __forceinline__ void ldsm4(uint32_t& r0, uint32_t& r1,
                                      uint32_t& r2, uint32_t& r3, uint32_t addr)
{
    asm volatile("ldmatrix.sync.aligned.m8n8.x4.shared.b16 {%0,%1,%2,%3}, [%4];"
                 : "=r"(r0), "=r"(r1), "=r"(r2), "=r"(r3) : "r"(addr));
}

// ===========================================================================
// FEED-EXPERIMENT GEMM (in_proj): 64x128 CTA tile, 8 warps of 32x32,
// 3 CTAs/SM (24 warps = 6/SMSP). Same bf16x3 math, bit-identical ordering.
// Stage: Ah/Al 64x80 B, Bh/Bl 128x80 B -> 30720 B; double-buffered 61440 B.
// ===========================================================================
#define ASTG 5120
#define BSTG 10240

__global__ __launch_bounds__(256, 3)
void gemm_bf16x3_t64(const bf16* __restrict__ Ahg, const bf16* __restrict__ Alg,
                     const bf16* __restrict__ Bhg, const bf16* __restrict__ Blg,
                     float* __restrict__ C, int ldc, int ldk, int K)
{
    extern __shared__ char sm[];
    const uint32_t sbase = (uint32_t)__cvta_generic_to_shared(sm);
    const uint32_t oAh = 0, oAl = 2 * ASTG, oBh = 4 * ASTG, oBl = 4 * ASTG + 2 * BSTG;

    const int tid  = threadIdx.x;
    const int warp = tid >> 5, lane = tid & 31;
    const int wm = (warp & 1) * 32;     // 2 warps in m (64)
    const int wn = (warp >> 1) * 32;    // 4 warps in n (128)
    const int g  = lane >> 2;
    const int tg = lane & 3;
    const int row0 = blockIdx.y * 64;
    const int col0 = blockIdx.x * 128;

    // loaders: A 64 rows x 64B (1 CP16/thread/array); B 128 rows x 64B (2 CP16)
    const int lrowA = tid >> 2;
    const int lcbA  = (tid & 3) * 8;    // bf16 col (16B units)
    const int lrowB = tid >> 1;
    const int lcbB  = (tid & 1) * 16;   // bf16 col (32B)

    const int lrA  = lane & 15;
    const int lkA  = (lane >> 4) * 16;
    const int lrB  = (lane & 7) + ((lane >> 4) << 3);
    const int lkB  = ((lane >> 3) & 1) * 16;

    float acc[2][4][4] = {};
    const int iters = K / 32;

    auto load_tile = [&](int tile) {
        const int s = tile & 1;
        const int k0 = tile * 32;
        CP16(sbase + oAh + s * ASTG + lrowA * 80 + lcbA * 2,
             Ahg + (size_t)(row0 + lrowA) * ldk + k0 + lcbA);
        CP16(sbase + oAl + s * ASTG + lrowA * 80 + lcbA * 2,
             Alg + (size_t)(row0 + lrowA) * ldk + k0 + lcbA);
        {
            const bf16* p = Bhg + (size_t)(col0 + lrowB) * ldk + k0 + lcbB;
            uint32_t d = sbase + oBh + s * BSTG + lrowB * 80 + lcbB * 2;
            CP16(d, p); CP16(d + 16, p + 8);
        }
        {
            const bf16* p = Blg + (size_t)(col0 + lrowB) * ldk + k0 + lcbB;
            uint32_t d = sbase + oBl + s * BSTG + lrowB * 80 + lcbB * 2;
            CP16(d, p); CP16(d + 16, p + 8);
        }
        asm volatile("cp.async.commit_group;");
    };

    load_tile(0);

    for (int it = 0; it < iters; ++it) {
        if (it + 1 < iters) {
            load_tile(it + 1);
            asm volatile("cp.async.wait_group 1;");
        } else {
            asm volatile("cp.async.wait_group 0;");
        }
        __syncthreads();

        const int s = it & 1;
        const uint32_t bAh = sbase + oAh + s * ASTG;
        const uint32_t bAl = sbase + oAl + s * ASTG;
        const uint32_t bBh = sbase + oBh + s * BSTG;
        const uint32_t bBl = sbase + oBl + s * BSTG;

#pragma unroll
        for (int ks = 0; ks < 2; ++ks) {
            const int kb = ks * 32;
            uint32_t ah[2][4], al[2][4], bh[4][2], bl[4][2];
#pragma unroll
            for (int mt = 0; mt < 2; ++mt) {
                const uint32_t ra = (wm + mt * 16 + lrA) * 80 + kb + lkA;
                ldsm4(ah[mt][0], ah[mt][1], ah[mt][2], ah[mt][3], bAh + ra);
                ldsm4(al[mt][0], al[mt][1], al[mt][2], al[mt][3], bAl + ra);
            }
#pragma unroll
            for (int np = 0; np < 2; ++np) {
                const uint32_t rb = (wn + np * 16 + lrB) * 80 + kb + lkB;
                ldsm4(bh[2*np][0], bh[2*np][1], bh[2*np+1][0], bh[2*np+1][1], bBh + rb);
                ldsm4(bl[2*np][0], bl[2*np][1], bl[2*np+1][0], bl[2*np+1][1], bBl + rb);
            }
#pragma unroll
            for (int mt = 0; mt < 2; ++mt)
#pragma unroll
                for (int nt = 0; nt < 4; ++nt)
                    mma_bf16(acc[mt][nt], al[mt], bh[nt]);
#pragma unroll
            for (int mt = 0; mt < 2; ++mt)
#pragma unroll
                for (int nt = 0; nt < 4; ++nt)
                    mma_bf16(acc[mt][nt], ah[mt], bl[nt]);
#pragma unroll
            for (int mt = 0; mt < 2; ++mt)
#pragma unroll
                for (int nt = 0; nt < 4; ++nt)
                    mma_bf16(acc[mt][nt], ah[mt], bh[nt]);
        }
        __syncthreads();
    }

#pragma unroll
    for (int mt = 0; mt < 2; ++mt) {
#pragma unroll
        for (int nt = 0; nt < 4; ++nt) {
            const int gr = row0 + wm + mt * 16 + g;
            const int gc = col0 + wn + nt * 8 + tg * 2;
            *(float2*)&C[(size_t)gr * ldc + gc] =
                make_float2(acc[mt][nt][0], acc[mt][nt][1]);
            *(float2*)&C[(size_t)(gr + 8) * ldc + gc] =
                make_float2(acc[mt][nt][2], acc[mt][nt][3]);
        }
    }
}

// ===========================================================================
// Proven mma.sync bf16x3 GEMM (out_proj / x_proj / dt_proj): 128x128 tile,
// 8 warps of 64x32, BK=32, 2-stage cp.async, 2 CTAs/SM.
// ===========================================================================
#define BM3 128
#define BN3 128
#define BK3 32
#define ROWB 80
#define TSB (128 * ROWB)

template <int MODE, int SPLITK>
__global__ __launch_bounds__(256, 2)
void gemm_bf16x3(const bf16* __restrict__ Ahg, const bf16* __restrict__ Alg,
                 const bf16* __restrict__ Bhg, const bf16* __restrict__ Blg,
                 float* __restrict__ C, int ldc, int ldk, int kcount,
                 size_t zstride, const float* __restrict__ bias)
{
    extern __shared__ char sm[];
    const uint32_t sbase = (uint32_t)__cvta_generic_to_shared(sm);
    const uint32_t oAh = 0, oAl = 2 * TSB, oBh = 4 * TSB, oBl = 6 * TSB;

    const int tid  = threadIdx.x;
    const int warp = tid >> 5, lane = tid & 31;
    const int wm = (warp & 1) * 64;
    const int wn = (warp >> 1) * 32;
    const int g  = lane >> 2;
    const int tg = lane & 3;
    const int row0 = blockIdx.y * BM3;
    const int col0 = blockIdx.x * BN3;
    const int kbeg = (SPLITK > 1) ? blockIdx.z * kcount : 0;
    if (SPLITK > 1) C += (size_t)blockIdx.z * zstride;

    const int lrow = tid >> 1;
    const int lcb  = (tid & 1) * 16;

    const int lrA  = lane & 15;
    const int lkA  = (lane >> 4) * 16;
    const int lrB  = (lane & 7) + ((lane >> 4) << 3);
    const int lkB  = ((lane >> 3) & 1) * 16;

    float acc[4][4][4] = {};
    const int iters = kcount / BK3;

    auto load_tile = [&](int tile) {
        const int s = tile & 1;
        const int k0 = kbeg + tile * BK3;
        {
            const bf16* p = Ahg + (size_t)(row0 + lrow) * ldk + k0 + lcb;
            uint32_t d = sbase + oAh + s * TSB + lrow * ROWB + lcb * 2;
            CP16(d, p); CP16(d + 16, p + 8);
        }
        {
            const bf16* p = Alg + (size_t)(row0 + lrow) * ldk + k0 + lcb;
            uint32_t d = sbase + oAl + s * TSB + lrow * ROWB + lcb * 2;
            CP16(d, p); CP16(d + 16, p + 8);
        }
        {
            const bf16* p = Bhg + (size_t)(col0 + lrow) * ldk + k0 + lcb;
            uint32_t d = sbase + oBh + s * TSB + lrow * ROWB + lcb * 2;
            CP16(d, p); CP16(d + 16, p + 8);
        }
        {
            const bf16* p = Blg + (size_t)(col0 + lrow) * ldk + k0 + lcb;
            uint32_t d = sbase + oBl + s * TSB + lrow * ROWB + lcb * 2;
            CP16(d, p); CP16(d + 16, p + 8);
        }
        asm volatile("cp.async.commit_group;");
    };

    load_tile(0);

    for (int it = 0; it < iters; ++it) {
        if (it + 1 < iters) {
            load_tile(it + 1);
            asm volatile("cp.async.wait_group 1;");
        } else {
            asm volatile("cp.async.wait_group 0;");
        }
        __syncthreads();

        const int s = it & 1;
        const uint32_t bAh = sbase + oAh + s * TSB;
        const uint32_t bAl = sbase + oAl + s * TSB;
        const uint32_t bBh = sbase + oBh + s * TSB;
        const uint32_t bBl = sbase + oBl + s * TSB;

#pragma unroll
        for (int ks = 0; ks < 2; ++ks) {
            const int kb = ks * 32;
            uint32_t ah[4][4], al[4][4], bh[4][2], bl[4][2];
#pragma unroll
            for (int mt = 0; mt < 4; ++mt) {
                const uint32_t ra = (wm + mt * 16 + lrA) * ROWB + kb + lkA;
                ldsm4(ah[mt][0], ah[mt][1], ah[mt][2], ah[mt][3], bAh + ra);
                ldsm4(al[mt][0], al[mt][1], al[mt][2], al[mt][3], bAl + ra);
            }
#pragma unroll
            for (int np = 0; np < 2; ++np) {
                const uint32_t rb = (wn + np * 16 + lrB) * ROWB + kb + lkB;
                ldsm4(bh[2*np][0], bh[2*np][1], bh[2*np+1][0], bh[2*np+1][1], bBh + rb);
                ldsm4(bl[2*np][0], bl[2*np][1], bl[2*np+1][0], bl[2*np+1][1], bBl + rb);
            }
#pragma unroll
            for (int mt = 0; mt < 4; ++mt)
#pragma unroll
                for (int nt = 0; nt < 4; ++nt)
                    mma_bf16(acc[mt][nt], al[mt], bh[nt]);
#pragma unroll
            for (int mt = 0; mt < 4; ++mt)
#pragma unroll
                for (int nt = 0; nt < 4; ++nt)
                    mma_bf16(acc[mt][nt], ah[mt], bl[nt]);
#pragma unroll
            for (int mt = 0; mt < 4; ++mt)
#pragma unroll
                for (int nt = 0; nt < 4; ++nt)
                    mma_bf16(acc[mt][nt], ah[mt], bh[nt]);
        }
        __syncthreads();
    }

    if (MODE == 0) {
#pragma unroll
        for (int mt = 0; mt < 4; ++mt) {
#pragma unroll
            for (int nt = 0; nt < 4; ++nt) {
                const int gr = row0 + wm + mt * 16 + g;
                const int gc = col0 + wn + nt * 8 + tg * 2;
                *(float2*)&C[(size_t)gr * ldc + gc] =
                    make_float2(acc[mt][nt][0], acc[mt][nt][1]);
                *(float2*)&C[(size_t)(gr + 8) * ldc + gc] =
                    make_float2(acc[mt][nt][2], acc[mt][nt][3]);
            }
        }
    } else {
        float (*st)[133] = (float(*)[133])sm;
#pragma unroll
        for (int mt = 0; mt < 4; ++mt) {
#pragma unroll
            for (int nt = 0; nt < 4; ++nt) {
                const int lr = wm + mt * 16 + g;
                const int lc = wn + nt * 8 + tg * 2;
                const float b0 = bias[col0 + lc];
                const float b1 = bias[col0 + lc + 1];
                st[lr][lc]          = softplusf(acc[mt][nt][0] + b0);
                st[lr][lc + 1]      = softplusf(acc[mt][nt][1] + b1);
                st[lr + 8][lc]      = softplusf(acc[mt][nt][2] + b0);
                st[lr + 8][lc + 1]  = softplusf(acc[mt][nt][3] + b1);
            }
        }
        __syncthreads();
#pragma unroll
        for (int ci = 0; ci < 16; ++ci) {
            const int c = warp + ci * 8;
            float* dst = C + (size_t)(col0 + c) * MM + row0;
#pragma unroll
            for (int k = 0; k < 4; ++k)
                dst[32 * k + lane] = st[32 * k + lane][c];
        }
    }
}

// ---------------------------------------------------------------------------
__global__ void reduce_out(const float* __restrict__ part,
                           float* __restrict__ out, int n4)
{
    int i = blockIdx.x * blockDim.x + threadIdx.x;
    if (i >= n4) return;
    const float4* p0 = (const float4*)part;
    const float4* p1 = p0 + n4;
    float4 a = p0[i], b = p1[i];
    ((float4*)out)[i] = make_float4(a.x + b.x, a.y + b.y, a.z + b.z, a.w + b.w);
}

// x_proj reduce over [z][M][NXP] partials -> xdbl[M,96]; fused dt split.
__global__ void reduce_sk(const float* __restrict__ part,
                          float* __restrict__ out,
                          bf16* __restrict__ dth, bf16* __restrict__ dtl, int n)
{
    int i = blockIdx.x * blockDim.x + threadIdx.x;
    if (i >= n) return;
    int row = i / 96;
    int col = i % 96;
    float s = 0.f;
#pragma unroll
    for (int z = 0; z < GG; z++)
        s += part[(size_t)z * MM * NXP + (size_t)row * NXP + col];
    out[i] = s;
    if (col < DTR) {
        bf16 h = __float2bfloat16(s);
        dth[(size_t)row * DTR + col] = h;
        dtl[(size_t)row * DTR + col] = __float2bfloat16(s - __bfloat162float(h));
    }
}

// ---------------------------------------------------------------------------
// Causal depthwise conv1d (k=4) + SiLU, tiled (validated R12 version).
// ---------------------------------------------------------------------------
__global__ __launch_bounds__(256)
void conv_silu_tr(const float* __restrict__ xzres,
                  const float* __restrict__ w,
                  const float* __restrict__ cb,
                  float* __restrict__ xc,
                  float* __restrict__ xcT,
                  float* __restrict__ sresT)
{
    __shared__ float sxz[36][33];
    __shared__ float sout[32][33];
    __shared__ float sres[32][33];

    const int d0 = blockIdx.x * 32;
    const int t0 = blockIdx.y * 32;
    const int b  = blockIdx.z;
    const int lane = threadIdx.x & 31;
    const int ty   = threadIdx.x >> 5;
    const size_t rs = 2 * DI;

    for (int r = ty; r < 35; r += 8) {
        int t = t0 - 3 + r;
        float v = 0.f;
        if (t >= 0) v = xzres[((size_t)(b * LL + t)) * rs + d0 + lane];
        sxz[r][lane] = v;
    }
    for (int r = ty; r < 32; r += 8) {
        int t = t0 + r;
        float v = xzres[((size_t)(b * LL + t)) * rs + DI + d0 + lane];
        sres[r][lane] = v / (1.f + __expf(-v));
    }
    __syncthreads();

    float wv[KC];
#pragma unroll
    for (int i = 0; i < KC; i++) wv[i] = w[(d0 + lane) * KC + i];
    const float bias = cb[d0 + lane];

    for (int r = ty; r < 32; r += 8) {
        float acc = bias;
#pragma unroll
        for (int i = 0; i < KC; i++)
            acc = fmaf(sxz[r + i][lane], wv[i], acc);
        float s = acc / (1.f + __expf(-acc));
        sout[r][lane] = s;
        xc[((size_t)(b * LL + t0 + r)) * DI + d0 + lane] = s;
    }
    __syncthreads();

    for (int r = ty; r < 32; r += 8) {
        xcT  [((size_t)(d0 + r)) * MM + b * LL + t0 + lane] = sout[lane][r];
        sresT[((size_t)(d0 + r)) * MM + b * LL + t0 + lane] = sres[lane][r];
    }
}

// ---------------------------------------------------------------------------
// Block-parallel selective scan, G=8 groups of 128 t (3 passes).
// ---------------------------------------------------------------------------
__global__ __launch_bounds__(256)
void scan_pass1(const float* __restrict__ deltaT,
                const float* __restrict__ xcT,
                const float* __restrict__ xdbl,
                const float* __restrict__ A_log,
                float* __restrict__ hend, float* __restrict__ sdlv)
{
    __shared__ float sB[GT][16];

    const int bx = blockIdx.x;
    const int dchunk = bx & 63;
    const int g = (bx >> 6) & (GG - 1);
    const int b = bx >> 9;
    const int n8 = threadIdx.x & 7;
    const int d = dchunk * 32 + (threadIdx.x >> 3);

    const float* xdB = xdbl + (size_t)b * LL * 96 + DTR;
    for (int i = threadIdx.x; i < GT * 16; i += 256) {
        int tt = i >> 4, c = i & 15;
        sB[tt][c] = xdB[(size_t)(g * GT + tt) * 96 + c];
    }
    __syncthreads();

    const float Adn0 = -expf(A_log[d * NS + n8]);
    const float Adn1 = -expf(A_log[d * NS + n8 + 8]);
    float h0 = 0.f, h1 = 0.f, sdl = 0.f;

    const size_t base = (size_t)d * MM + (size_t)b * LL + g * GT;
    const float4* dT4 = (const float4*)(deltaT + base);
    const float4* uT4 = (const float4*)(xcT + base);

    for (int tb = 0; tb < GT; tb += 4) {
        float4 dl4 = dT4[tb >> 2];
        float4 u4  = uT4[tb >> 2];
        float dls[4] = {dl4.x, dl4.y, dl4.z, dl4.w};
        float us[4]  = {u4.x,  u4.y,  u4.z,  u4.w};
#pragma unroll
        for (int j = 0; j < 4; j++) {
            const int tt = tb + j;
            float dl = dls[j];
            sdl += dl;
            float db = dl * us[j];
            h0 = fmaf(__expf(dl * Adn0), h0, db * sB[tt][n8]);
            h1 = fmaf(__expf(dl * Adn1), h1, db * sB[tt][n8 + 8]);
        }
    }
    const size_t o = (((size_t)b * DI + d) * GG + g) * NS;
    hend[o + n8] = h0;
    hend[o + n8 + 8] = h1;
    if (n8 == 0) sdlv[((size_t)b * DI + d) * GG + g] = sdl;
}

__global__ void scan_pass2(const float* __restrict__ hend,
                           const float* __restrict__ sdlv,
                           const float* __restrict__ A_log,
                           float* __restrict__ hcar)
{
    int tid = blockIdx.x * blockDim.x + threadIdx.x;
    int n = tid & 15;
    int d = (tid >> 4) & (DI - 1);
    int b = tid >> 15;
    const float Adn = -expf(A_log[d * NS + n]);
    float H = 0.f;
    const size_t ob = ((size_t)b * DI + d) * GG;
    for (int g = 0; g < GG; g++) {
        hcar[(ob + g) * NS + n] = H;
        H = fmaf(__expf(Adn * sdlv[ob + g]), H, hend[(ob + g) * NS + n]);
    }
}

__global__ __launch_bounds__(256)
void scan_pass3(const float* __restrict__ deltaT,
                const float* __restrict__ xcT,
                const float* __restrict__ sresT,
                const float* __restrict__ xdbl,
                const float* __restrict__ A_log,
                const float* __restrict__ Dp,
                const float* __restrict__ hcar,
                bf16* __restrict__ yh, bf16* __restrict__ yl)
{
    __shared__ float sBC[GT][32];

    const int bx = blockIdx.x;
    const int dchunk = bx & 63;
    const int g = (bx >> 6) & (GG - 1);
    const int b = bx >> 9;
    const int n8 = threadIdx.x & 7;
    const int d = dchunk * 32 + (threadIdx.x >> 3);

    const float* xdBC = xdbl + (size_t)b * LL * 96 + DTR;
    for (int i = threadIdx.x; i < GT * 32; i += 256) {
        int tt = i >> 5, c = i & 31;
        sBC[tt][c] = xdBC[(size_t)(g * GT + tt) * 96 + c];
    }
    __syncthreads();

    const float Adn0 = -expf(A_log[d * NS + n8]);
    const float Adn1 = -expf(A_log[d * NS + n8 + 8]);
    const float Dd = Dp[d];
    const size_t oc = (((size_t)b * DI + d) * GG + g) * NS;
    float h0 = hcar[oc + n8];
    float h1 = hcar[oc + n8 + 8];

    const size_t base = (size_t)d * MM + (size_t)b * LL + g * GT;
    const float4* dT4 = (const float4*)(deltaT + base);
    const float4* uT4 = (const float4*)(xcT + base);
    const float4* sT4 = (const float4*)(sresT + base);
    const size_t ybase = ((size_t)b * LL + g * GT) * DI + d;

    for (int tb = 0; tb < GT; tb += 4) {
        float4 dl4 = dT4[tb >> 2];
        float4 u4  = uT4[tb >> 2];
        float4 s4  = sT4[tb >> 2];
        float dls[4] = {dl4.x, dl4.y, dl4.z, dl4.w};
        float us[4]  = {u4.x,  u4.y,  u4.z,  u4.w};
        float ss[4]  = {s4.x,  s4.y,  s4.z,  s4.w};
        float yp[4];

#pragma unroll
        for (int j = 0; j < 4; j++) {
            const int tt = tb + j;
            float Bv0 = sBC[tt][n8];
            float Bv1 = sBC[tt][n8 + 8];
            float Cv0 = sBC[tt][n8 + 16];
            float Cv1 = sBC[tt][n8 + 24];
            float dl = dls[j];
            float e0 = __expf(dl * Adn0);
            float e1 = __expf(dl * Adn1);
            float db = dl * us[j];
            h0 = fmaf(e0, h0, db * Bv0);
            h1 = fmaf(e1, h1, db * Bv1);
            yp[j] = fmaf(h0, Cv0, h1 * Cv1);
        }

#pragma unroll
        for (int j = 0; j < 4; j++) yp[j] += __shfl_xor_sync(0xffffffffu, yp[j], 4);
#pragma unroll
        for (int j = 0; j < 4; j++) yp[j] += __shfl_xor_sync(0xffffffffu, yp[j], 2);
#pragma unroll
        for (int j = 0; j < 4; j++) yp[j] += __shfl_xor_sync(0xffffffffu, yp[j], 1);

        if (n8 == 0) {
#pragma unroll
            for (int j = 0; j < 4; j++) {
                float w = (yp[j] + us[j] * Dd) * ss[j];
                bf16 hb = __float2bfloat16(w);
                const size_t off = ybase + (size_t)(tb + j) * DI;
                yh[off] = hb;
                yl[off] = __float2bfloat16(w - __bfloat162float(hb));
            }
        }
    }
}

// ---------------------------------------------------------------------------
extern "C" void kernel_launch(void* const* d_in, const int* in_sizes, int n_in,
                              void* d_out, int out_size)
{
    const float* x      = (const float*)d_in[0];
    const float* W_in   = (const float*)d_in[1];
    const float* conv_w = (const float*)d_in[2];
    const float* conv_b = (const float*)d_in[3];
    const float* W_x    = (const float*)d_in[4];
    const float* W_dt   = (const float*)d_in[5];
    const float* b_dt   = (const float*)d_in[6];
    const float* A_log  = (const float*)d_in[7];
    const float* Dp     = (const float*)d_in[8];
    const float* W_out  = (const float*)d_in[9];
    float* out = (float*)d_out;

    float *p_xzres, *p_xc, *p_xcT, *p_sresT, *p_xdbl, *p_xpart, *p_opart, *p_deltaT;
    float *p_hend, *p_hcar, *p_sdl;
    bf16 *p_xh, *p_xl, *p_Winh, *p_Winl, *p_Wouth, *p_Woutl;
    bf16 *p_Wxh, *p_Wxl, *p_Wdth, *p_Wdtl, *p_xch, *p_xcl, *p_dth, *p_dtl, *p_yh, *p_yl;
    cudaGetSymbolAddress((void**)&p_xzres,  g_xzres);
    cudaGetSymbolAddress((void**)&p_xc,     g_xc);
    cudaGetSymbolAddress((void**)&p_xcT,    g_xcT);
    cudaGetSymbolAddress((void**)&p_sresT,  g_sresT);
    cudaGetSymbolAddress((void**)&p_xdbl,   g_xdbl);
    cudaGetSymbolAddress((void**)&p_xpart,  g_xpart);
    cudaGetSymbolAddress((void**)&p_opart,  g_opart);
    cudaGetSymbolAddress((void**)&p_deltaT, g_deltaT);
    cudaGetSymbolAddress((void**)&p_hend,   g_hend);
    cudaGetSymbolAddress((void**)&p_hcar,   g_hcar);
    cudaGetSymbolAddress((void**)&p_sdl,    g_sdl);
    cudaGetSymbolAddress((void**)&p_xh,     g_xh);
    cudaGetSymbolAddress((void**)&p_xl,     g_xl);
    cudaGetSymbolAddress((void**)&p_Winh,   g_Winh);
    cudaGetSymbolAddress((void**)&p_Winl,   g_Winl);
    cudaGetSymbolAddress((void**)&p_Wouth,  g_Wouth);
    cudaGetSymbolAddress((void**)&p_Woutl,  g_Woutl);
    cudaGetSymbolAddress((void**)&p_Wxh,    g_Wxh);
    cudaGetSymbolAddress((void**)&p_Wxl,    g_Wxl);
    cudaGetSymbolAddress((void**)&p_Wdth,   g_Wdth);
    cudaGetSymbolAddress((void**)&p_Wdtl,   g_Wdtl);
    cudaGetSymbolAddress((void**)&p_xch,    g_xch);
    cudaGetSymbolAddress((void**)&p_xcl,    g_xcl);
    cudaGetSymbolAddress((void**)&p_dth,    g_dth);
    cudaGetSymbolAddress((void**)&p_dtl,    g_dtl);
    cudaGetSymbolAddress((void**)&p_yh,     g_yh);
    cudaGetSymbolAddress((void**)&p_yl,     g_yl);

    cudaFuncSetAttribute(gemm_bf16x3_t64,
                         cudaFuncAttributeMaxDynamicSharedMemorySize, 4 * ASTG + 4 * BSTG);
    cudaFuncSetAttribute(gemm_bf16x3<0, 2>,
                         cudaFuncAttributeMaxDynamicSharedMemorySize, 8 * TSB);
    cudaFuncSetAttribute(gemm_bf16x3<0, 8>,
                         cudaFuncAttributeMaxDynamicSharedMemorySize, 8 * TSB);
    cudaFuncSetAttribute(gemm_bf16x3<1, 1>,
                         cudaFuncAttributeMaxDynamicSharedMemorySize, 8 * TSB);

    // 0) fused bf16 hi/lo split of x, W_in, W_out, W_dt, W_x (one launch)
    split_all<<<(SEG4 + 255) / 256, 256>>>(
        x, W_in, W_out, W_dt, W_x,
        p_xh, p_xl, p_Winh, p_Winl, p_Wouth, p_Woutl,
        p_Wdth, p_Wdtl, p_Wxh, p_Wxl);

    // 1) in_proj (bf16x3, 64x128 tiles, 3 CTAs/SM): xzres = x @ W_in^T
    gemm_bf16x3_t64<<<dim3(2 * DI / 128, MM / 64), 256, 4 * ASTG + 4 * BSTG>>>(
        p_xh, p_xl, p_Winh, p_Winl, p_xzres, 2 * DI, DM, DM);

    // 2) causal conv + silu -> xc (fp32) + xcT + sresT
    conv_silu_tr<<<dim3(DI / 32, LL / 32, BB), 256>>>(
        p_xzres, conv_w, conv_b, p_xc, p_xcT, p_sresT);

    // 2b) standalone bf16 split of xc for the x_proj tensor GEMM
    split_xc<<<(MM * DI / 4) / 256, 256>>>(p_xc, p_xch, p_xcl, MM * DI / 4);

    // 3) x_proj (bf16x3, split-K x8, padded N=128) + reduce (fused dt split)
    gemm_bf16x3<0, 8><<<dim3(1, MM / BM3, GG), 256, 8 * TSB>>>(
        p_xch, p_xcl, p_Wxh, p_Wxl, p_xpart, NXP, DI, DI / GG,
        (size_t)MM * NXP, nullptr);
    reduce_sk<<<(MM * 96) / 256, 256>>>(p_xpart, p_xdbl, p_dth, p_dtl, MM * 96);

    // 4) dt_proj (bf16x3, fused softplus + transposed store): deltaT[DI,M]
    gemm_bf16x3<1, 1><<<dim3(DI / BN3, MM / BM3), 256, 8 * TSB>>>(
        p_dth, p_dtl, p_Wdth, p_Wdtl, p_deltaT, 0, DTR, DTR, 0, b_dt);

    // 5) block-parallel selective scan (3 passes) -> y (bf16 hi/lo)
    scan_pass1<<<BB * GG * (DI / 32), 256>>>(
        p_deltaT, p_xcT, p_xdbl, A_log, p_hend, p_sdl);
    scan_pass2<<<(BB * DI * NS) / 256, 256>>>(p_hend, p_sdl, A_log, p_hcar);
    scan_pass3<<<BB * GG * (DI / 32), 256>>>(
        p_deltaT, p_xcT, p_sresT, p_xdbl, A_log, Dp, p_hcar, p_yh, p_yl);

    // 6) out_proj (bf16x3, split-K x2) + reduce -> out
    gemm_bf16x3<0, 2><<<dim3(DM / BN3, MM / BM3, 2), 256, 8 * TSB>>>(
        p_yh, p_yl, p_Wouth, p_Woutl, p_opart, DM, DI, DI / 2,
        (size_t)MM * DM, nullptr);
    reduce_out<<<(MM * DM / 4) / 256, 256>>>(p_opart, out, MM * DM / 4);
}